// round 9
// baseline (speedup 1.0000x reference)
#include <cuda_runtime.h>
#include <cuda_fp16.h>
#include <math.h>
#include <stddef.h>
#include <stdint.h>

#define NN   100000
#define EE   800000
#define CH   256
#define COUT 40
#define BN_EPS 1e-5f
#define SCAN_BLK 1024
#define NSCAN ((NN + SCAN_BLK - 1) / SCAN_BLK)  // 98

// ---------------- scratch (device globals) ----------------
__device__ __half2 g_t[(size_t)NN * CH / 2];  // GEMM output (fp16 pairs)
__device__ float g_agg[(size_t)NN * CH];      // aggregated (GCN output pre-BN)
__device__ float g_dis[NN];
__device__ float g_wsum[NN];
__device__ int   g_deg[NN];
__device__ int   g_rowptr[NN + 1];
__device__ int   g_cursor[NN];
__device__ int   g_csr_src[EE];
__device__ int   g_partials[256];
__device__ float g_stats[2 * CH];
__device__ float g_bn_a[CH];
__device__ float g_bn_b[CH];
__device__ float g_pool[CH];
__device__ float g_vx[CH];
__device__ float g_rowvec[CH];
__device__ float g_s[CH];
__device__ float g_z[CH];

// ---------------- helpers ----------------
__device__ __forceinline__ uint32_t f2tf32(float x) {
    uint32_t u;
    asm("cvt.rna.tf32.f32 %0, %1;" : "=r"(u) : "f"(x));
    return u;
}

__device__ __forceinline__ void mma_tf32(float& c0, float& c1, float& c2, float& c3,
                                         uint32_t a0, uint32_t a1, uint32_t a2, uint32_t a3,
                                         uint32_t b0, uint32_t b1) {
    asm volatile("mma.sync.aligned.m16n8k8.row.col.f32.tf32.tf32.f32 "
                 "{%0,%1,%2,%3}, {%4,%5,%6,%7}, {%8,%9}, {%0,%1,%2,%3};"
                 : "+f"(c0), "+f"(c1), "+f"(c2), "+f"(c3)
                 : "r"(a0), "r"(a1), "r"(a2), "r"(a3), "r"(b0), "r"(b1));
}

// ---------------- degree / init ----------------
__global__ void zero_deg_kernel(int* __restrict__ deg, float* __restrict__ stats,
                                float* __restrict__ pool, float* __restrict__ rowvec) {
    int i = blockIdx.x * blockDim.x + threadIdx.x;
    if (i < NN) deg[i] = 0;
    if (i < CH) {
        stats[i] = 0.f;
        stats[i + CH] = 0.f;
        pool[i] = 0.f;
        rowvec[i] = 0.f;
    }
}
__global__ void count_deg_kernel(const int* __restrict__ dst, int* __restrict__ deg) {
    int e = blockIdx.x * blockDim.x + threadIdx.x;
    if (e < EE) atomicAdd(&deg[dst[e]], 1);
}
__global__ void compute_dis_kernel(const int* __restrict__ deg, float* __restrict__ dis) {
    int i = blockIdx.x * blockDim.x + threadIdx.x;
    if (i < NN) dis[i] = rsqrtf((float)deg[i] + 1.0f);
}

// wsum[n] = dis[n] * (dis[n] + sum_{e into n} dis[src])
__global__ void compute_wsum_kernel(const int* __restrict__ rp, const int* __restrict__ csr,
                                    const float* __restrict__ dis, float* __restrict__ wsum) {
    int n = blockIdx.x * blockDim.x + threadIdx.x;
    if (n >= NN) return;
    float dn = dis[n];
    float s = dn;
    int e1 = rp[n + 1];
    for (int e = rp[n]; e < e1; e++) s += dis[csr[e]];
    wsum[n] = dn * s;
}

// ---------------- exclusive scan (3 phases) ----------------
__global__ void scan1_kernel(const int* __restrict__ deg, int* __restrict__ rp,
                             int* __restrict__ partials) {
    __shared__ int sm[256];
    int tid = threadIdx.x;
    int base = blockIdx.x * SCAN_BLK + tid * 4;
    int v[4];
    int s = 0;
#pragma unroll
    for (int i = 0; i < 4; i++) {
        v[i] = (base + i < NN) ? deg[base + i] : 0;
        s += v[i];
    }
    sm[tid] = s;
    __syncthreads();
#pragma unroll
    for (int off = 1; off < 256; off <<= 1) {
        int tv = (tid >= off) ? sm[tid - off] : 0;
        __syncthreads();
        sm[tid] += tv;
        __syncthreads();
    }
    int excl = sm[tid] - s;
    if (tid == 255) partials[blockIdx.x] = sm[255];
    int run = excl;
#pragma unroll
    for (int i = 0; i < 4; i++) {
        if (base + i < NN) rp[base + i] = run;
        run += v[i];
    }
}

__global__ void scan2_kernel(int* __restrict__ partials) {
    __shared__ int sm[128];
    int tid = threadIdx.x;
    int v = (tid < NSCAN) ? partials[tid] : 0;
    sm[tid] = v;
    __syncthreads();
#pragma unroll
    for (int off = 1; off < 128; off <<= 1) {
        int tv = (tid >= off) ? sm[tid - off] : 0;
        __syncthreads();
        sm[tid] += tv;
        __syncthreads();
    }
    if (tid < NSCAN) partials[tid] = sm[tid] - v;
}

__global__ void scan3_kernel(int* __restrict__ rp, const int* __restrict__ partials,
                             int* __restrict__ cursor) {
    int tid = threadIdx.x;
    int base = blockIdx.x * SCAN_BLK + tid * 4;
    int off = partials[blockIdx.x];
#pragma unroll
    for (int i = 0; i < 4; i++) {
        int idx = base + i;
        if (idx < NN) {
            int val = rp[idx] + off;
            rp[idx] = val;
            cursor[idx] = val;
        }
    }
    if (blockIdx.x == 0 && tid == 0) rp[NN] = EE;
}

__global__ void fill_csr_kernel(const int* __restrict__ src, const int* __restrict__ dst,
                                int* __restrict__ cursor, int* __restrict__ csr) {
    int e = blockIdx.x * blockDim.x + threadIdx.x;
    if (e >= EE) return;
    int slot = atomicAdd(&cursor[dst[e]], 1);
    csr[slot] = src[e];
}

// ---------------- tf32 tensor-core GEMM, fp16 output ----------------
// t = op(A) @ B;  op(A) optionally BN+ReLU per column; optionally accumulates
// pool[c] = sum_rows relu(bn(A)) (blockIdx.x==0 blocks only).
template <int BN_T, bool APPLY_BN, bool POOL>
__global__ void __launch_bounds__(256, 2)
mma_gemm_kernel(const float* __restrict__ A, const float* __restrict__ B,
                const float* __restrict__ bn_a, const float* __restrict__ bn_b,
                __half2* __restrict__ Tout, float* __restrict__ pool,
                int M, int Ncols, int K) {
    constexpr int BM = 128, BK = 32;
    constexpr int AS_STRIDE = BK + 4;
    constexpr int BS_STRIDE = BN_T + 8;
    __shared__ uint32_t As[BM * AS_STRIDE];
    __shared__ uint32_t Bs[BK * BS_STRIDE];
    __shared__ float spool[256];

    const int tid = threadIdx.x;
    const int wid = tid >> 5, lane = tid & 31;
    const int gid = lane >> 2, tig = lane & 3;
    const int wm = wid & 3, wn = wid >> 2;
    constexpr int WM = 32, WN = BN_T / 2;
    constexpr int MT = WM / 16;
    constexpr int NT = WN / 8;
    const int m0 = blockIdx.y * BM, n0 = blockIdx.x * BN_T;
    const bool do_pool = POOL && (blockIdx.x == 0);

    if (POOL) {
        spool[tid] = 0.f;
        __syncthreads();
    }

    float acc[MT][NT][4];
#pragma unroll
    for (int i = 0; i < MT; i++)
#pragma unroll
        for (int j = 0; j < NT; j++)
#pragma unroll
            for (int q = 0; q < 4; q++) acc[i][j][q] = 0.0f;

    for (int k0 = 0; k0 < K; k0 += BK) {
        float pv0 = 0.f, pv1 = 0.f, pv2 = 0.f, pv3 = 0.f;
#pragma unroll
        for (int j = 0; j < (BM * BK) / (256 * 4); j++) {
            int idx = tid + j * 256;
            int r = idx >> 3, c4 = (idx & 7) * 4;
            int row = m0 + r;
            float4 v = make_float4(0.f, 0.f, 0.f, 0.f);
            if (row < M)
                v = *reinterpret_cast<const float4*>(&A[(size_t)row * K + k0 + c4]);
            if (APPLY_BN) {
                v.x = fmaxf(fmaf(v.x, bn_a[k0 + c4 + 0], bn_b[k0 + c4 + 0]), 0.f);
                v.y = fmaxf(fmaf(v.y, bn_a[k0 + c4 + 1], bn_b[k0 + c4 + 1]), 0.f);
                v.z = fmaxf(fmaf(v.z, bn_a[k0 + c4 + 2], bn_b[k0 + c4 + 2]), 0.f);
                v.w = fmaxf(fmaf(v.w, bn_a[k0 + c4 + 3], bn_b[k0 + c4 + 3]), 0.f);
                if (POOL && do_pool && row < M) {
                    pv0 += v.x; pv1 += v.y; pv2 += v.z; pv3 += v.w;
                }
            }
            uint4 u = make_uint4(f2tf32(v.x), f2tf32(v.y), f2tf32(v.z), f2tf32(v.w));
            *reinterpret_cast<uint4*>(&As[r * AS_STRIDE + c4]) = u;
        }
        if (POOL && do_pool) {
            int c4 = (tid & 7) * 4;
            atomicAdd(&spool[k0 + c4 + 0], pv0);
            atomicAdd(&spool[k0 + c4 + 1], pv1);
            atomicAdd(&spool[k0 + c4 + 2], pv2);
            atomicAdd(&spool[k0 + c4 + 3], pv3);
        }
#pragma unroll
        for (int j = 0; j < (BK * BN_T) / (256 * 4); j++) {
            int idx = tid + j * 256;
            int kr = idx / (BN_T / 4), c4 = (idx % (BN_T / 4)) * 4;
            int col = n0 + c4;
            float4 v = make_float4(0.f, 0.f, 0.f, 0.f);
            if (col + 4 <= Ncols)
                v = *reinterpret_cast<const float4*>(&B[(size_t)(k0 + kr) * Ncols + col]);
            uint4 u = make_uint4(f2tf32(v.x), f2tf32(v.y), f2tf32(v.z), f2tf32(v.w));
            *reinterpret_cast<uint4*>(&Bs[kr * BS_STRIDE + c4]) = u;
        }
        __syncthreads();

#pragma unroll
        for (int k8 = 0; k8 < BK; k8 += 8) {
            uint32_t bf[NT][2];
#pragma unroll
            for (int nt = 0; nt < NT; nt++) {
                int ncol = wn * WN + nt * 8 + gid;
                bf[nt][0] = Bs[(k8 + tig) * BS_STRIDE + ncol];
                bf[nt][1] = Bs[(k8 + tig + 4) * BS_STRIDE + ncol];
            }
#pragma unroll
            for (int mt = 0; mt < MT; mt++) {
                int mrow = wm * WM + mt * 16 + gid;
                uint32_t a0 = As[mrow * AS_STRIDE + k8 + tig];
                uint32_t a1 = As[(mrow + 8) * AS_STRIDE + k8 + tig];
                uint32_t a2 = As[mrow * AS_STRIDE + k8 + tig + 4];
                uint32_t a3 = As[(mrow + 8) * AS_STRIDE + k8 + tig + 4];
#pragma unroll
                for (int nt = 0; nt < NT; nt++)
                    mma_tf32(acc[mt][nt][0], acc[mt][nt][1], acc[mt][nt][2], acc[mt][nt][3],
                             a0, a1, a2, a3, bf[nt][0], bf[nt][1]);
            }
        }
        __syncthreads();
    }

    if (POOL && do_pool) {
        // all spool atomics complete (last __syncthreads above)
        atomicAdd(&pool[tid], spool[tid]);
    }

    const int nc2 = Ncols / 2;
#pragma unroll
    for (int mt = 0; mt < MT; mt++) {
        int r0 = m0 + wm * WM + mt * 16 + gid;
        int r1 = r0 + 8;
#pragma unroll
        for (int nt = 0; nt < NT; nt++) {
            int col = n0 + wn * WN + nt * 8 + tig * 2;
            if (col + 2 > Ncols) continue;
            if (r0 < M)
                Tout[(size_t)r0 * nc2 + (col >> 1)] =
                    __floats2half2_rn(acc[mt][nt][0], acc[mt][nt][1]);
            if (r1 < M)
                Tout[(size_t)r1 * nc2 + (col >> 1)] =
                    __floats2half2_rn(acc[mt][nt][2], acc[mt][nt][3]);
        }
    }
}

// ---------------- CSR gather aggregation (wide, C=256, fp16 t) + BN stats ----------------
#define GW 8  // nodes per half-block (block = 2 half-blocks of 128 threads)
__global__ void __launch_bounds__(256)
gather_wide_kernel(const int* __restrict__ rp, const int* __restrict__ csr,
                   const float* __restrict__ dis, const float* __restrict__ wsum,
                   const __half2* __restrict__ t2,
                   const float* __restrict__ rowvec, const float* __restrict__ bias,
                   float* __restrict__ agg, float* __restrict__ stats) {
    const int hb = threadIdx.x >> 7;
    const int c2 = threadIdx.x & 127;
    const int c = c2 * 2;
    const float2 rv = *reinterpret_cast<const float2*>(&rowvec[c]);
    const float2 bi = *reinterpret_cast<const float2*>(&bias[c]);
    float s1x = 0.f, s1y = 0.f, s2x = 0.f, s2y = 0.f;
    int n0 = blockIdx.x * (2 * GW) + hb * GW;
#pragma unroll 1
    for (int g = 0; g < GW; g++) {
        int n = n0 + g;
        if (n >= NN) break;
        float dn = dis[n];
        float ws = wsum[n];
        float2 tv = __half22float2(t2[(size_t)n * 128 + c2]);
        float a0 = fmaf(tv.x, dn * dn, fmaf(rv.x, ws, bi.x));
        float a1 = fmaf(tv.y, dn * dn, fmaf(rv.y, ws, bi.y));
        int e = rp[n], e1 = rp[n + 1];
        for (; e + 2 <= e1; e += 2) {
            int sa = csr[e];
            int sb = csr[e + 1];
            float ca = dis[sa] * dn;
            float cb = dis[sb] * dn;
            float2 va = __half22float2(t2[(size_t)sa * 128 + c2]);
            float2 vb = __half22float2(t2[(size_t)sb * 128 + c2]);
            a0 = fmaf(va.x, ca, a0);
            a1 = fmaf(va.y, ca, a1);
            a0 = fmaf(vb.x, cb, a0);
            a1 = fmaf(vb.y, cb, a1);
        }
        if (e < e1) {
            int sa = csr[e];
            float ca = dis[sa] * dn;
            float2 va = __half22float2(t2[(size_t)sa * 128 + c2]);
            a0 = fmaf(va.x, ca, a0);
            a1 = fmaf(va.y, ca, a1);
        }
        *reinterpret_cast<float2*>(&agg[(size_t)n * CH + c]) = make_float2(a0, a1);
        s1x += a0; s2x += a0 * a0;
        s1y += a1; s2y += a1 * a1;
    }
    atomicAdd(&stats[c], s1x);
    atomicAdd(&stats[c + 1], s1y);
    atomicAdd(&stats[CH + c], s2x);
    atomicAdd(&stats[CH + c + 1], s2y);
}

// ---------------- BN finalize (also zeroes pool for next GEMM-side accumulation) ----------------
__global__ void finalize_stats_kernel(const float* __restrict__ stats,
                                      const float* __restrict__ g, const float* __restrict__ bv,
                                      float* __restrict__ bn_a, float* __restrict__ bn_b,
                                      float* __restrict__ pool) {
    int c = threadIdx.x;
    float m = stats[c] * (1.0f / (float)NN);
    float v = stats[CH + c] * (1.0f / (float)NN) - m * m;
    float a = rsqrtf(v + BN_EPS) * g[c];
    bn_a[c] = a;
    bn_b[c] = bv[c] - m * a;
    pool[c] = 0.f;
}

// ---------------- virtual-node MLP ----------------
__global__ void vn_prep_kernel(const float* __restrict__ pool, const float* __restrict__ vx_prev,
                               const float* __restrict__ vnb,
                               float* __restrict__ s, float* __restrict__ z) {
    int c = threadIdx.x;
    s[c] = pool[c] + vx_prev[c];
    z[c] = vnb[c];
}

__global__ void vn_matvec_kernel(const float* __restrict__ s, const float* __restrict__ W,
                                 float* __restrict__ z, int cols) {
    __shared__ float ss[32];
    int c = threadIdx.x;
    int kb = blockIdx.x * 32;
    if (c < 32) ss[c] = s[kb + c];
    __syncthreads();
    if (c < cols) {
        float acc = 0.f;
#pragma unroll
        for (int k = 0; k < 32; k++) acc = fmaf(ss[k], W[(size_t)(kb + k) * cols + c], acc);
        atomicAdd(&z[c], acc);
    }
}

// LayerNorm+ReLU; zeroes stats (next gather) and rowvec (next rowvec accumulation)
__global__ void vn_ln_kernel(const float* __restrict__ z,
                             const float* __restrict__ lng, const float* __restrict__ lnb,
                             float* __restrict__ vx_out, float* __restrict__ rowvec,
                             float* __restrict__ stats) {
    __shared__ float red[CH];
    int c = threadIdx.x;
    float zv = z[c];
    red[c] = zv;
    __syncthreads();
    for (int off = CH / 2; off; off >>= 1) {
        if (c < off) red[c] += red[c + off];
        __syncthreads();
    }
    float mu = red[0] * (1.0f / (float)CH);
    __syncthreads();
    float d = zv - mu;
    red[c] = d * d;
    __syncthreads();
    for (int off = CH / 2; off; off >>= 1) {
        if (c < off) red[c] += red[c + off];
        __syncthreads();
    }
    float var = red[0] * (1.0f / (float)CH);
    vx_out[c] = fmaxf(fmaf(d * rsqrtf(var + BN_EPS), lng[c], lnb[c]), 0.f);
    rowvec[c] = 0.f;
    stats[c] = 0.f;
    stats[CH + c] = 0.f;
}

__global__ void rowvec_matvec_kernel(const float* __restrict__ vx, const float* __restrict__ W,
                                     float* __restrict__ rowvec, int cols) {
    __shared__ float ss[32];
    int c = threadIdx.x;
    int kb = blockIdx.x * 32;
    if (c < 32) ss[c] = vx[kb + c];
    __syncthreads();
    if (c < cols) {
        float acc = 0.f;
#pragma unroll
        for (int k = 0; k < 32; k++) acc = fmaf(ss[k], W[(size_t)(kb + k) * cols + c], acc);
        atomicAdd(&rowvec[c], acc);
    }
}

// ---------------- final layer: CSR gather (C=40, fp16 t) + log_softmax ----------------
__global__ void __launch_bounds__(256)
gather_out_kernel(const int* __restrict__ rp, const int* __restrict__ csr,
                  const float* __restrict__ dis, const float* __restrict__ wsum,
                  const __half2* __restrict__ t2,
                  const float* __restrict__ rowvec, const float* __restrict__ bias,
                  float* __restrict__ out) {
    int warp = threadIdx.x >> 5;
    int lane = threadIdx.x & 31;
    int n = blockIdx.x * 8 + warp;
    if (n >= NN) return;
    const bool act = (lane < COUT / 2);  // 20 active lanes, 2 channels each
    const int c = lane * 2;

    float dn = dis[n];
    float ws = wsum[n];
    float a0 = -1e30f, a1 = -1e30f;
    float2 rv = make_float2(0.f, 0.f), bi = make_float2(0.f, 0.f);
    if (act) {
        rv = *reinterpret_cast<const float2*>(&rowvec[c]);
        bi = *reinterpret_cast<const float2*>(&bias[c]);
        float2 tv = __half22float2(t2[(size_t)n * (COUT / 2) + lane]);
        a0 = fmaf(tv.x, dn * dn, fmaf(rv.x, ws, bi.x));
        a1 = fmaf(tv.y, dn * dn, fmaf(rv.y, ws, bi.y));
    }

    int e = rp[n], e1 = rp[n + 1];
    for (; e < e1; e++) {
        int sa = csr[e];
        float ca = dis[sa] * dn;
        if (act) {
            float2 va = __half22float2(t2[(size_t)sa * (COUT / 2) + lane]);
            a0 = fmaf(va.x, ca, a0);
            a1 = fmaf(va.y, ca, a1);
        }
    }

    float m = fmaxf(a0, a1);
#pragma unroll
    for (int off = 16; off; off >>= 1) m = fmaxf(m, __shfl_xor_sync(0xffffffffu, m, off));
    float sum = act ? (expf(a0 - m) + expf(a1 - m)) : 0.f;
#pragma unroll
    for (int off = 16; off; off >>= 1) sum += __shfl_xor_sync(0xffffffffu, sum, off);
    float l = m + logf(sum);
    if (act)
        *reinterpret_cast<float2*>(&out[(size_t)n * COUT + c]) = make_float2(a0 - l, a1 - l);
}

// ---------------- driver ----------------
extern "C" void kernel_launch(void* const* d_in, const int* in_sizes, int n_in,
                              void* d_out, int out_size) {
    const float* x      = (const float*)d_in[0];
    const int*   ei     = (const int*)d_in[1];
    const float* W0     = (const float*)d_in[2];
    const float* b0     = (const float*)d_in[3];
    const float* W1     = (const float*)d_in[4];
    const float* b1     = (const float*)d_in[5];
    const float* W2     = (const float*)d_in[6];
    const float* b2     = (const float*)d_in[7];
    const float* bn_g0  = (const float*)d_in[8];
    const float* bn_b0  = (const float*)d_in[9];
    const float* bn_g1  = (const float*)d_in[10];
    const float* bn_b1  = (const float*)d_in[11];
    const float* vn_emb = (const float*)d_in[12];
    const float* vn_W0  = (const float*)d_in[13];
    const float* vn_b0  = (const float*)d_in[14];
    const float* ln_g0  = (const float*)d_in[15];
    const float* ln_b0  = (const float*)d_in[16];
    const float* vn_W1  = (const float*)d_in[17];
    const float* vn_b1  = (const float*)d_in[18];
    const float* ln_g1  = (const float*)d_in[19];
    const float* ln_b1  = (const float*)d_in[20];
    float* out = (float*)d_out;

    const int* src = ei;
    const int* dst = ei + EE;

    float *agg, *dis, *wsum, *stats, *bn_a, *bn_b, *pool, *vx, *rowvec, *s, *z;
    __half2* t2;
    int *deg, *rowptr, *cursor, *csr, *partials;
    cudaGetSymbolAddress((void**)&t2, g_t);
    cudaGetSymbolAddress((void**)&agg, g_agg);
    cudaGetSymbolAddress((void**)&dis, g_dis);
    cudaGetSymbolAddress((void**)&wsum, g_wsum);
    cudaGetSymbolAddress((void**)&deg, g_deg);
    cudaGetSymbolAddress((void**)&rowptr, g_rowptr);
    cudaGetSymbolAddress((void**)&cursor, g_cursor);
    cudaGetSymbolAddress((void**)&csr, g_csr_src);
    cudaGetSymbolAddress((void**)&partials, g_partials);
    cudaGetSymbolAddress((void**)&stats, g_stats);
    cudaGetSymbolAddress((void**)&bn_a, g_bn_a);
    cudaGetSymbolAddress((void**)&bn_b, g_bn_b);
    cudaGetSymbolAddress((void**)&pool, g_pool);
    cudaGetSymbolAddress((void**)&vx, g_vx);
    cudaGetSymbolAddress((void**)&rowvec, g_rowvec);
    cudaGetSymbolAddress((void**)&s, g_s);
    cudaGetSymbolAddress((void**)&z, g_z);

    const int T = 256;
    dim3 gemm_wide(CH / 128, (NN + 127) / 128);
    dim3 gemm_narrow(1, (NN + 127) / 128);
    int gather_blocks = (NN + 2 * GW - 1) / (2 * GW);

    // ---- CSR build + normalization ----
    zero_deg_kernel<<<(NN + T - 1) / T, T>>>(deg, stats, pool, rowvec);
    count_deg_kernel<<<(EE + T - 1) / T, T>>>(dst, deg);
    compute_dis_kernel<<<(NN + T - 1) / T, T>>>(deg, dis);
    scan1_kernel<<<NSCAN, 256>>>(deg, rowptr, partials);
    scan2_kernel<<<1, 128>>>(partials);
    scan3_kernel<<<NSCAN, 256>>>(rowptr, partials, cursor);
    fill_csr_kernel<<<(EE + T - 1) / T, T>>>(src, dst, cursor, csr);
    compute_wsum_kernel<<<(NN + T - 1) / T, T>>>(rowptr, csr, dis, wsum);

    // ---- layer 0 ----
    rowvec_matvec_kernel<<<8, T>>>(vn_emb, W0, rowvec, CH);  // rowvec0 = vn_emb @ W0
    mma_gemm_kernel<128, false, false><<<gemm_wide, T>>>(x, W0, nullptr, nullptr,
                                                         t2, pool, NN, CH, CH);
    gather_wide_kernel<<<gather_blocks, T>>>(rowptr, csr, dis, wsum, t2, rowvec, b0, agg, stats);
    finalize_stats_kernel<<<1, T>>>(stats, bn_g0, bn_b0, bn_a, bn_b, pool);

    // ---- layer 1 GEMM (computes pool0 as byproduct) ----
    mma_gemm_kernel<128, true, true><<<gemm_wide, T>>>(agg, W1, bn_a, bn_b,
                                                       t2, pool, NN, CH, CH);
    vn_prep_kernel<<<1, T>>>(pool, vn_emb, vn_b0, s, z);
    vn_matvec_kernel<<<8, T>>>(s, vn_W0, z, CH);
    vn_ln_kernel<<<1, T>>>(z, ln_g0, ln_b0, vx, rowvec, stats);
    rowvec_matvec_kernel<<<8, T>>>(vx, W1, rowvec, CH);       // rowvec1 = vx1 @ W1
    gather_wide_kernel<<<gather_blocks, T>>>(rowptr, csr, dis, wsum, t2, rowvec, b1, agg, stats);
    finalize_stats_kernel<<<1, T>>>(stats, bn_g1, bn_b1, bn_a, bn_b, pool);

    // ---- layer 2 GEMM (computes pool1 as byproduct) ----
    mma_gemm_kernel<64, true, true><<<gemm_narrow, T>>>(agg, W2, bn_a, bn_b,
                                                        t2, pool, NN, COUT, CH);
    vn_prep_kernel<<<1, T>>>(pool, vx, vn_b1, s, z);
    vn_matvec_kernel<<<8, T>>>(s, vn_W1, z, CH);
    vn_ln_kernel<<<1, T>>>(z, ln_g1, ln_b1, vx, rowvec, stats);
    rowvec_matvec_kernel<<<8, T>>>(vx, W2, rowvec, COUT);     // rowvec2 = vx2 @ W2
    gather_out_kernel<<<(NN + 7) / 8, T>>>(rowptr, csr, dis, wsum, t2, rowvec, b2, out);
}

// round 10
// speedup vs baseline: 1.0016x; 1.0016x over previous
#include <cuda_runtime.h>
#include <cuda_fp16.h>
#include <math.h>
#include <stddef.h>
#include <stdint.h>

#define NN   100000
#define EE   800000
#define CH   256
#define COUT 40
#define BN_EPS 1e-5f
#define SCAN_BLK 1024
#define NSCAN ((NN + SCAN_BLK - 1) / SCAN_BLK)  // 98

// ---------------- scratch (device globals) ----------------
__device__ __half2 g_t[(size_t)NN * CH / 2];  // GEMM output, pre-scaled by dis[row], fp16 pairs
__device__ float g_agg[(size_t)NN * CH];      // aggregated (GCN output pre-BN)
__device__ float g_dis[NN];
__device__ int   g_deg[NN];
__device__ int   g_rowptr[NN + 1];
__device__ int   g_cursor[NN];
__device__ int   g_csr_src[EE];
__device__ int   g_partials[256];
__device__ float g_stats[2 * CH];
__device__ float g_bn_a[CH];
__device__ float g_bn_b[CH];
__device__ float g_pool[CH];
__device__ float g_vx[CH];
__device__ float g_rowvec[CH];
__device__ float g_s[CH];
__device__ float g_z[CH];

// ---------------- helpers ----------------
__device__ __forceinline__ uint32_t f2tf32(float x) {
    uint32_t u;
    asm("cvt.rna.tf32.f32 %0, %1;" : "=r"(u) : "f"(x));
    return u;
}

__device__ __forceinline__ void mma_tf32(float& c0, float& c1, float& c2, float& c3,
                                         uint32_t a0, uint32_t a1, uint32_t a2, uint32_t a3,
                                         uint32_t b0, uint32_t b1) {
    asm volatile("mma.sync.aligned.m16n8k8.row.col.f32.tf32.tf32.f32 "
                 "{%0,%1,%2,%3}, {%4,%5,%6,%7}, {%8,%9}, {%0,%1,%2,%3};"
                 : "+f"(c0), "+f"(c1), "+f"(c2), "+f"(c3)
                 : "r"(a0), "r"(a1), "r"(a2), "r"(a3), "r"(b0), "r"(b1));
}

// ---------------- degree / init ----------------
__global__ void zero_deg_kernel(int* __restrict__ deg, float* __restrict__ stats,
                                float* __restrict__ pool, float* __restrict__ rowvec) {
    int i = blockIdx.x * blockDim.x + threadIdx.x;
    if (i < NN) deg[i] = 0;
    if (i < CH) {
        stats[i] = 0.f;
        stats[i + CH] = 0.f;
        pool[i] = 0.f;
        rowvec[i] = 0.f;
    }
}
__global__ void count_deg_kernel(const int* __restrict__ dst, int* __restrict__ deg) {
    int e = blockIdx.x * blockDim.x + threadIdx.x;
    if (e < EE) atomicAdd(&deg[dst[e]], 1);
}
__global__ void compute_dis_kernel(const int* __restrict__ deg, float* __restrict__ dis) {
    int i = blockIdx.x * blockDim.x + threadIdx.x;
    if (i < NN) dis[i] = rsqrtf((float)deg[i] + 1.0f);
}

// ---------------- exclusive scan (3 phases) ----------------
__global__ void scan1_kernel(const int* __restrict__ deg, int* __restrict__ rp,
                             int* __restrict__ partials) {
    __shared__ int sm[256];
    int tid = threadIdx.x;
    int base = blockIdx.x * SCAN_BLK + tid * 4;
    int v[4];
    int s = 0;
#pragma unroll
    for (int i = 0; i < 4; i++) {
        v[i] = (base + i < NN) ? deg[base + i] : 0;
        s += v[i];
    }
    sm[tid] = s;
    __syncthreads();
#pragma unroll
    for (int off = 1; off < 256; off <<= 1) {
        int tv = (tid >= off) ? sm[tid - off] : 0;
        __syncthreads();
        sm[tid] += tv;
        __syncthreads();
    }
    int excl = sm[tid] - s;
    if (tid == 255) partials[blockIdx.x] = sm[255];
    int run = excl;
#pragma unroll
    for (int i = 0; i < 4; i++) {
        if (base + i < NN) rp[base + i] = run;
        run += v[i];
    }
}

__global__ void scan2_kernel(int* __restrict__ partials) {
    __shared__ int sm[128];
    int tid = threadIdx.x;
    int v = (tid < NSCAN) ? partials[tid] : 0;
    sm[tid] = v;
    __syncthreads();
#pragma unroll
    for (int off = 1; off < 128; off <<= 1) {
        int tv = (tid >= off) ? sm[tid - off] : 0;
        __syncthreads();
        sm[tid] += tv;
        __syncthreads();
    }
    if (tid < NSCAN) partials[tid] = sm[tid] - v;
}

__global__ void scan3_kernel(int* __restrict__ rp, const int* __restrict__ partials,
                             int* __restrict__ cursor) {
    int tid = threadIdx.x;
    int base = blockIdx.x * SCAN_BLK + tid * 4;
    int off = partials[blockIdx.x];
#pragma unroll
    for (int i = 0; i < 4; i++) {
        int idx = base + i;
        if (idx < NN) {
            int val = rp[idx] + off;
            rp[idx] = val;
            cursor[idx] = val;
        }
    }
    if (blockIdx.x == 0 && tid == 0) rp[NN] = EE;
}

__global__ void fill_csr_kernel(const int* __restrict__ src, const int* __restrict__ dst,
                                int* __restrict__ cursor, int* __restrict__ csr) {
    int e = blockIdx.x * blockDim.x + threadIdx.x;
    if (e >= EE) return;
    int slot = atomicAdd(&cursor[dst[e]], 1);
    csr[slot] = src[e];
}

// ---------------- tf32 tensor-core GEMM, fp16 dis-scaled output ----------------
// t'[m] = ((op(A) @ B)[m] + rowvec) * dis[m]; op(A) optionally BN+ReLU per column.
template <int BN_T, bool APPLY_BN>
__global__ void __launch_bounds__(256, 2)
mma_gemm_kernel(const float* __restrict__ A, const float* __restrict__ B,
                const float* __restrict__ rowvec, const float* __restrict__ dis,
                const float* __restrict__ bn_a, const float* __restrict__ bn_b,
                __half2* __restrict__ Tout,
                int M, int Ncols, int K) {
    constexpr int BM = 128, BK = 32;
    constexpr int AS_STRIDE = BK + 4;
    constexpr int BS_STRIDE = BN_T + 8;
    __shared__ uint32_t As[BM * AS_STRIDE];
    __shared__ uint32_t Bs[BK * BS_STRIDE];

    const int tid = threadIdx.x;
    const int wid = tid >> 5, lane = tid & 31;
    const int gid = lane >> 2, tig = lane & 3;
    const int wm = wid & 3, wn = wid >> 2;
    constexpr int WM = 32, WN = BN_T / 2;
    constexpr int MT = WM / 16;
    constexpr int NT = WN / 8;
    const int m0 = blockIdx.y * BM, n0 = blockIdx.x * BN_T;

    float acc[MT][NT][4];
#pragma unroll
    for (int i = 0; i < MT; i++)
#pragma unroll
        for (int j = 0; j < NT; j++)
#pragma unroll
            for (int q = 0; q < 4; q++) acc[i][j][q] = 0.0f;

    for (int k0 = 0; k0 < K; k0 += BK) {
#pragma unroll
        for (int j = 0; j < (BM * BK) / (256 * 4); j++) {
            int idx = tid + j * 256;
            int r = idx >> 3, c4 = (idx & 7) * 4;
            int row = m0 + r;
            float4 v = make_float4(0.f, 0.f, 0.f, 0.f);
            if (row < M)
                v = *reinterpret_cast<const float4*>(&A[(size_t)row * K + k0 + c4]);
            if (APPLY_BN) {
                v.x = fmaxf(fmaf(v.x, bn_a[k0 + c4 + 0], bn_b[k0 + c4 + 0]), 0.f);
                v.y = fmaxf(fmaf(v.y, bn_a[k0 + c4 + 1], bn_b[k0 + c4 + 1]), 0.f);
                v.z = fmaxf(fmaf(v.z, bn_a[k0 + c4 + 2], bn_b[k0 + c4 + 2]), 0.f);
                v.w = fmaxf(fmaf(v.w, bn_a[k0 + c4 + 3], bn_b[k0 + c4 + 3]), 0.f);
            }
            uint4 u = make_uint4(f2tf32(v.x), f2tf32(v.y), f2tf32(v.z), f2tf32(v.w));
            *reinterpret_cast<uint4*>(&As[r * AS_STRIDE + c4]) = u;
        }
#pragma unroll
        for (int j = 0; j < (BK * BN_T) / (256 * 4); j++) {
            int idx = tid + j * 256;
            int kr = idx / (BN_T / 4), c4 = (idx % (BN_T / 4)) * 4;
            int col = n0 + c4;
            float4 v = make_float4(0.f, 0.f, 0.f, 0.f);
            if (col + 4 <= Ncols)
                v = *reinterpret_cast<const float4*>(&B[(size_t)(k0 + kr) * Ncols + col]);
            uint4 u = make_uint4(f2tf32(v.x), f2tf32(v.y), f2tf32(v.z), f2tf32(v.w));
            *reinterpret_cast<uint4*>(&Bs[kr * BS_STRIDE + c4]) = u;
        }
        __syncthreads();

#pragma unroll
        for (int k8 = 0; k8 < BK; k8 += 8) {
            uint32_t bf[NT][2];
#pragma unroll
            for (int nt = 0; nt < NT; nt++) {
                int ncol = wn * WN + nt * 8 + gid;
                bf[nt][0] = Bs[(k8 + tig) * BS_STRIDE + ncol];
                bf[nt][1] = Bs[(k8 + tig + 4) * BS_STRIDE + ncol];
            }
#pragma unroll
            for (int mt = 0; mt < MT; mt++) {
                int mrow = wm * WM + mt * 16 + gid;
                uint32_t a0 = As[mrow * AS_STRIDE + k8 + tig];
                uint32_t a1 = As[(mrow + 8) * AS_STRIDE + k8 + tig];
                uint32_t a2 = As[mrow * AS_STRIDE + k8 + tig + 4];
                uint32_t a3 = As[(mrow + 8) * AS_STRIDE + k8 + tig + 4];
#pragma unroll
                for (int nt = 0; nt < NT; nt++)
                    mma_tf32(acc[mt][nt][0], acc[mt][nt][1], acc[mt][nt][2], acc[mt][nt][3],
                             a0, a1, a2, a3, bf[nt][0], bf[nt][1]);
            }
        }
        __syncthreads();
    }

    const int nc2 = Ncols / 2;
#pragma unroll
    for (int mt = 0; mt < MT; mt++) {
        int r0 = m0 + wm * WM + mt * 16 + gid;
        int r1 = r0 + 8;
        float d0 = (r0 < M) ? dis[r0] : 0.f;
        float d1 = (r1 < M) ? dis[r1] : 0.f;
#pragma unroll
        for (int nt = 0; nt < NT; nt++) {
            int col = n0 + wn * WN + nt * 8 + tig * 2;
            if (col + 2 > Ncols) continue;
            float2 rv = *reinterpret_cast<const float2*>(&rowvec[col]);
            if (r0 < M)
                Tout[(size_t)r0 * nc2 + (col >> 1)] =
                    __floats2half2_rn((acc[mt][nt][0] + rv.x) * d0,
                                      (acc[mt][nt][1] + rv.y) * d0);
            if (r1 < M)
                Tout[(size_t)r1 * nc2 + (col >> 1)] =
                    __floats2half2_rn((acc[mt][nt][2] + rv.x) * d1,
                                      (acc[mt][nt][3] + rv.y) * d1);
        }
    }
}

// ---------------- CSR gather aggregation (C=256, dis-scaled fp16 t) + BN stats ----------------
// agg[n] = dis[n] * (t'[n] + sum_src t'[src]) + bias   (coefficient factored out)
#define GW 8  // nodes per half-block; block = 2 half-blocks of 128 threads
__global__ void __launch_bounds__(256)
gather_wide_kernel(const int* __restrict__ rp, const int* __restrict__ csr,
                   const float* __restrict__ dis, const __half2* __restrict__ t2,
                   const float* __restrict__ bias,
                   float* __restrict__ agg, float* __restrict__ stats) {
    const int hb = threadIdx.x >> 7;
    const int c2 = threadIdx.x & 127;
    const int c = c2 * 2;
    const float2 bi = *reinterpret_cast<const float2*>(&bias[c]);
    float s1x = 0.f, s1y = 0.f, s2x = 0.f, s2y = 0.f;
    int n0 = blockIdx.x * (2 * GW) + hb * GW;
#pragma unroll 1
    for (int g = 0; g < GW; g++) {
        int n = n0 + g;
        if (n >= NN) break;
        float2 tv = __half22float2(t2[(size_t)n * 128 + c2]);
        float a0 = tv.x, a1 = tv.y;  // self term (already dis-scaled)
        int e = rp[n], e1 = rp[n + 1];
        for (; e + 2 <= e1; e += 2) {
            int sa = csr[e];
            int sb = csr[e + 1];
            float2 va = __half22float2(t2[(size_t)sa * 128 + c2]);
            float2 vb = __half22float2(t2[(size_t)sb * 128 + c2]);
            a0 += va.x + vb.x;
            a1 += va.y + vb.y;
        }
        if (e < e1) {
            int sa = csr[e];
            float2 va = __half22float2(t2[(size_t)sa * 128 + c2]);
            a0 += va.x;
            a1 += va.y;
        }
        float dn = dis[n];
        a0 = fmaf(a0, dn, bi.x);
        a1 = fmaf(a1, dn, bi.y);
        *reinterpret_cast<float2*>(&agg[(size_t)n * CH + c]) = make_float2(a0, a1);
        s1x += a0; s2x += a0 * a0;
        s1y += a1; s2y += a1 * a1;
    }
    atomicAdd(&stats[c], s1x);
    atomicAdd(&stats[c + 1], s1y);
    atomicAdd(&stats[CH + c], s2x);
    atomicAdd(&stats[CH + c + 1], s2y);
}

// ---------------- BN finalize / pool ----------------
__global__ void finalize_stats_kernel(const float* __restrict__ stats,
                                      const float* __restrict__ g, const float* __restrict__ bv,
                                      float* __restrict__ bn_a, float* __restrict__ bn_b) {
    int c = threadIdx.x;
    float m = stats[c] * (1.0f / (float)NN);
    float v = stats[CH + c] * (1.0f / (float)NN) - m * m;
    float a = rsqrtf(v + BN_EPS) * g[c];
    bn_a[c] = a;
    bn_b[c] = bv[c] - m * a;
}

__global__ void pool_kernel(const float* __restrict__ agg,
                            const float* __restrict__ bn_a, const float* __restrict__ bn_b,
                            float* __restrict__ pool) {
    int c = threadIdx.x;
    float a = bn_a[c], b = bn_b[c];
    float ps = 0.f;
    for (int r = blockIdx.x; r < NN; r += gridDim.x)
        ps += fmaxf(fmaf(agg[(size_t)r * CH + c], a, b), 0.f);
    atomicAdd(&pool[c], ps);
}

// ---------------- virtual-node MLP ----------------
__global__ void vn_prep_kernel(const float* __restrict__ pool, const float* __restrict__ vx_prev,
                               const float* __restrict__ vnb,
                               float* __restrict__ s, float* __restrict__ z) {
    int c = threadIdx.x;
    s[c] = pool[c] + vx_prev[c];
    z[c] = vnb[c];
}

__global__ void vn_matvec_kernel(const float* __restrict__ s, const float* __restrict__ W,
                                 float* __restrict__ z, int cols) {
    __shared__ float ss[32];
    int c = threadIdx.x;
    int kb = blockIdx.x * 32;
    if (c < 32) ss[c] = s[kb + c];
    __syncthreads();
    if (c < cols) {
        float acc = 0.f;
#pragma unroll
        for (int k = 0; k < 32; k++) acc = fmaf(ss[k], W[(size_t)(kb + k) * cols + c], acc);
        atomicAdd(&z[c], acc);
    }
}

// LayerNorm+ReLU; re-zeros stats/pool/rowvec for the next layer
__global__ void vn_ln_kernel(const float* __restrict__ z,
                             const float* __restrict__ lng, const float* __restrict__ lnb,
                             float* __restrict__ vx_out, float* __restrict__ rowvec,
                             float* __restrict__ stats, float* __restrict__ pool) {
    __shared__ float red[CH];
    int c = threadIdx.x;
    float zv = z[c];
    red[c] = zv;
    __syncthreads();
    for (int off = CH / 2; off; off >>= 1) {
        if (c < off) red[c] += red[c + off];
        __syncthreads();
    }
    float mu = red[0] * (1.0f / (float)CH);
    __syncthreads();
    float d = zv - mu;
    red[c] = d * d;
    __syncthreads();
    for (int off = CH / 2; off; off >>= 1) {
        if (c < off) red[c] += red[c + off];
        __syncthreads();
    }
    float var = red[0] * (1.0f / (float)CH);
    vx_out[c] = fmaxf(fmaf(d * rsqrtf(var + BN_EPS), lng[c], lnb[c]), 0.f);
    rowvec[c] = 0.f;
    stats[c] = 0.f;
    stats[CH + c] = 0.f;
    pool[c] = 0.f;
}

__global__ void rowvec_matvec_kernel(const float* __restrict__ vx, const float* __restrict__ W,
                                     float* __restrict__ rowvec, int cols) {
    __shared__ float ss[32];
    int c = threadIdx.x;
    int kb = blockIdx.x * 32;
    if (c < 32) ss[c] = vx[kb + c];
    __syncthreads();
    if (c < cols) {
        float acc = 0.f;
#pragma unroll
        for (int k = 0; k < 32; k++) acc = fmaf(ss[k], W[(size_t)(kb + k) * cols + c], acc);
        atomicAdd(&rowvec[c], acc);
    }
}

// ---------------- final layer: CSR gather (C=40, dis-scaled fp16 t) + log_softmax ----------------
__global__ void __launch_bounds__(256)
gather_out_kernel(const int* __restrict__ rp, const int* __restrict__ csr,
                  const float* __restrict__ dis, const __half2* __restrict__ t2,
                  const float* __restrict__ bias, float* __restrict__ out) {
    int warp = threadIdx.x >> 5;
    int lane = threadIdx.x & 31;
    int n = blockIdx.x * 8 + warp;
    if (n >= NN) return;
    const bool act = (lane < COUT / 2);  // 20 active lanes, 2 channels each
    const int c = lane * 2;

    float a0 = 0.f, a1 = 0.f;
    float2 bi = make_float2(0.f, 0.f);
    if (act) {
        bi = *reinterpret_cast<const float2*>(&bias[c]);
        float2 tv = __half22float2(t2[(size_t)n * (COUT / 2) + lane]);
        a0 = tv.x;
        a1 = tv.y;
    }

    int e = rp[n], e1 = rp[n + 1];
    for (; e < e1; e++) {
        int sa = csr[e];
        if (act) {
            float2 va = __half22float2(t2[(size_t)sa * (COUT / 2) + lane]);
            a0 += va.x;
            a1 += va.y;
        }
    }
    float dn = dis[n];
    if (act) {
        a0 = fmaf(a0, dn, bi.x);
        a1 = fmaf(a1, dn, bi.y);
    } else {
        a0 = -1e30f;
        a1 = -1e30f;
    }

    float m = fmaxf(a0, a1);
#pragma unroll
    for (int off = 16; off; off >>= 1) m = fmaxf(m, __shfl_xor_sync(0xffffffffu, m, off));
    float sum = act ? (expf(a0 - m) + expf(a1 - m)) : 0.f;
#pragma unroll
    for (int off = 16; off; off >>= 1) sum += __shfl_xor_sync(0xffffffffu, sum, off);
    float l = m + logf(sum);
    if (act)
        *reinterpret_cast<float2*>(&out[(size_t)n * COUT + c]) = make_float2(a0 - l, a1 - l);
}

// ---------------- driver ----------------
extern "C" void kernel_launch(void* const* d_in, const int* in_sizes, int n_in,
                              void* d_out, int out_size) {
    const float* x      = (const float*)d_in[0];
    const int*   ei     = (const int*)d_in[1];
    const float* W0     = (const float*)d_in[2];
    const float* b0     = (const float*)d_in[3];
    const float* W1     = (const float*)d_in[4];
    const float* b1     = (const float*)d_in[5];
    const float* W2     = (const float*)d_in[6];
    const float* b2     = (const float*)d_in[7];
    const float* bn_g0  = (const float*)d_in[8];
    const float* bn_b0  = (const float*)d_in[9];
    const float* bn_g1  = (const float*)d_in[10];
    const float* bn_b1  = (const float*)d_in[11];
    const float* vn_emb = (const float*)d_in[12];
    const float* vn_W0  = (const float*)d_in[13];
    const float* vn_b0  = (const float*)d_in[14];
    const float* ln_g0  = (const float*)d_in[15];
    const float* ln_b0  = (const float*)d_in[16];
    const float* vn_W1  = (const float*)d_in[17];
    const float* vn_b1  = (const float*)d_in[18];
    const float* ln_g1  = (const float*)d_in[19];
    const float* ln_b1  = (const float*)d_in[20];
    float* out = (float*)d_out;

    const int* src = ei;
    const int* dst = ei + EE;

    float *agg, *dis, *stats, *bn_a, *bn_b, *pool, *vx, *rowvec, *s, *z;
    __half2* t2;
    int *deg, *rowptr, *cursor, *csr, *partials;
    cudaGetSymbolAddress((void**)&t2, g_t);
    cudaGetSymbolAddress((void**)&agg, g_agg);
    cudaGetSymbolAddress((void**)&dis, g_dis);
    cudaGetSymbolAddress((void**)&deg, g_deg);
    cudaGetSymbolAddress((void**)&rowptr, g_rowptr);
    cudaGetSymbolAddress((void**)&cursor, g_cursor);
    cudaGetSymbolAddress((void**)&csr, g_csr_src);
    cudaGetSymbolAddress((void**)&partials, g_partials);
    cudaGetSymbolAddress((void**)&stats, g_stats);
    cudaGetSymbolAddress((void**)&bn_a, g_bn_a);
    cudaGetSymbolAddress((void**)&bn_b, g_bn_b);
    cudaGetSymbolAddress((void**)&pool, g_pool);
    cudaGetSymbolAddress((void**)&vx, g_vx);
    cudaGetSymbolAddress((void**)&rowvec, g_rowvec);
    cudaGetSymbolAddress((void**)&s, g_s);
    cudaGetSymbolAddress((void**)&z, g_z);

    const int T = 256;
    const int STAT_BLOCKS = 1024;
    dim3 gemm_wide(CH / 128, (NN + 127) / 128);
    dim3 gemm_narrow(1, (NN + 127) / 128);
    int gather_blocks = (NN + 2 * GW - 1) / (2 * GW);

    // ---- CSR build + normalization ----
    zero_deg_kernel<<<(NN + T - 1) / T, T>>>(deg, stats, pool, rowvec);
    count_deg_kernel<<<(EE + T - 1) / T, T>>>(dst, deg);
    compute_dis_kernel<<<(NN + T - 1) / T, T>>>(deg, dis);
    scan1_kernel<<<NSCAN, 256>>>(deg, rowptr, partials);
    scan2_kernel<<<1, 128>>>(partials);
    scan3_kernel<<<NSCAN, 256>>>(rowptr, partials, cursor);
    fill_csr_kernel<<<(EE + T - 1) / T, T>>>(src, dst, cursor, csr);

    // ---- layer 0 ----
    rowvec_matvec_kernel<<<8, T>>>(vn_emb, W0, rowvec, CH);
    mma_gemm_kernel<128, false><<<gemm_wide, T>>>(x, W0, rowvec, dis,
                                                  nullptr, nullptr, t2, NN, CH, CH);
    gather_wide_kernel<<<gather_blocks, T>>>(rowptr, csr, dis, t2, b0, agg, stats);
    finalize_stats_kernel<<<1, T>>>(stats, bn_g0, bn_b0, bn_a, bn_b);
    pool_kernel<<<STAT_BLOCKS, T>>>(agg, bn_a, bn_b, pool);
    vn_prep_kernel<<<1, T>>>(pool, vn_emb, vn_b0, s, z);
    vn_matvec_kernel<<<8, T>>>(s, vn_W0, z, CH);
    vn_ln_kernel<<<1, T>>>(z, ln_g0, ln_b0, vx, rowvec, stats, pool);
    rowvec_matvec_kernel<<<8, T>>>(vx, W1, rowvec, CH);

    // ---- layer 1 ----
    mma_gemm_kernel<128, true><<<gemm_wide, T>>>(agg, W1, rowvec, dis,
                                                 bn_a, bn_b, t2, NN, CH, CH);
    gather_wide_kernel<<<gather_blocks, T>>>(rowptr, csr, dis, t2, b1, agg, stats);
    finalize_stats_kernel<<<1, T>>>(stats, bn_g1, bn_b1, bn_a, bn_b);
    pool_kernel<<<STAT_BLOCKS, T>>>(agg, bn_a, bn_b, pool);
    vn_prep_kernel<<<1, T>>>(pool, vx, vn_b1, s, z);
    vn_matvec_kernel<<<8, T>>>(s, vn_W1, z, CH);
    vn_ln_kernel<<<1, T>>>(z, ln_g1, ln_b1, vx, rowvec, stats, pool);
    rowvec_matvec_kernel<<<8, T>>>(vx, W2, rowvec, COUT);

    // ---- layer 2 (output, fused gather + log_softmax) ----
    mma_gemm_kernel<64, true><<<gemm_narrow, T>>>(agg, W2, rowvec, dis,
                                                  bn_a, bn_b, t2, NN, COUT, CH);
    gather_out_kernel<<<(NN + 7) / 8, T>>>(rowptr, csr, dis, t2, b2, out);
}

// round 11
// speedup vs baseline: 1.2562x; 1.2542x over previous
#include <cuda_runtime.h>
#include <math.h>
#include <stddef.h>
#include <stdint.h>

#define NN   100000
#define EE   800000
#define CH   256
#define COUT 40
#define BN_EPS 1e-5f
#define SCAN_BLK 1024
#define NSCAN ((NN + SCAN_BLK - 1) / SCAN_BLK)  // 98

// ---------------- scratch (device globals) ----------------
__device__ float g_t[(size_t)NN * CH];    // GEMM output, pre-scaled by dis[row]
__device__ float g_agg[(size_t)NN * CH];  // aggregated (GCN output pre-BN)
__device__ float g_dis[NN];
__device__ int   g_deg[NN];
__device__ int   g_rowptr[NN + 1];
__device__ int   g_cursor[NN];
__device__ int   g_csr_src[EE];
__device__ int   g_partials[256];
__device__ float g_stats[2 * CH];
__device__ float g_bn_a[CH];
__device__ float g_bn_b[CH];
__device__ float g_pool[CH];
__device__ float g_vx[CH];
__device__ float g_rowvec[CH];
__device__ float g_z[CH];

// ---------------- helpers ----------------
__device__ __forceinline__ uint32_t f2tf32(float x) {
    uint32_t u;
    asm("cvt.rna.tf32.f32 %0, %1;" : "=r"(u) : "f"(x));
    return u;
}

__device__ __forceinline__ void mma_tf32(float& c0, float& c1, float& c2, float& c3,
                                         uint32_t a0, uint32_t a1, uint32_t a2, uint32_t a3,
                                         uint32_t b0, uint32_t b1) {
    asm volatile("mma.sync.aligned.m16n8k8.row.col.f32.tf32.tf32.f32 "
                 "{%0,%1,%2,%3}, {%4,%5,%6,%7}, {%8,%9}, {%0,%1,%2,%3};"
                 : "+f"(c0), "+f"(c1), "+f"(c2), "+f"(c3)
                 : "r"(a0), "r"(a1), "r"(a2), "r"(a3), "r"(b0), "r"(b1));
}

// ---------------- degree / init ----------------
__global__ void zero_deg_kernel(int* __restrict__ deg, float* __restrict__ stats,
                                float* __restrict__ pool, float* __restrict__ rowvec) {
    int i = blockIdx.x * blockDim.x + threadIdx.x;
    if (i < NN) deg[i] = 0;
    if (i < CH) {
        stats[i] = 0.f;
        stats[i + CH] = 0.f;
        pool[i] = 0.f;
        rowvec[i] = 0.f;
    }
}
__global__ void count_deg_kernel(const int* __restrict__ dst, int* __restrict__ deg) {
    int e = blockIdx.x * blockDim.x + threadIdx.x;
    if (e < EE) atomicAdd(&deg[dst[e]], 1);
}
__global__ void compute_dis_kernel(const int* __restrict__ deg, float* __restrict__ dis) {
    int i = blockIdx.x * blockDim.x + threadIdx.x;
    if (i < NN) dis[i] = rsqrtf((float)deg[i] + 1.0f);
}

// ---------------- exclusive scan (3 phases) ----------------
__global__ void scan1_kernel(const int* __restrict__ deg, int* __restrict__ rp,
                             int* __restrict__ partials) {
    __shared__ int sm[256];
    int tid = threadIdx.x;
    int base = blockIdx.x * SCAN_BLK + tid * 4;
    int v[4];
    int s = 0;
#pragma unroll
    for (int i = 0; i < 4; i++) {
        v[i] = (base + i < NN) ? deg[base + i] : 0;
        s += v[i];
    }
    sm[tid] = s;
    __syncthreads();
#pragma unroll
    for (int off = 1; off < 256; off <<= 1) {
        int tv = (tid >= off) ? sm[tid - off] : 0;
        __syncthreads();
        sm[tid] += tv;
        __syncthreads();
    }
    int excl = sm[tid] - s;
    if (tid == 255) partials[blockIdx.x] = sm[255];
    int run = excl;
#pragma unroll
    for (int i = 0; i < 4; i++) {
        if (base + i < NN) rp[base + i] = run;
        run += v[i];
    }
}

__global__ void scan2_kernel(int* __restrict__ partials) {
    __shared__ int sm[128];
    int tid = threadIdx.x;
    int v = (tid < NSCAN) ? partials[tid] : 0;
    sm[tid] = v;
    __syncthreads();
#pragma unroll
    for (int off = 1; off < 128; off <<= 1) {
        int tv = (tid >= off) ? sm[tid - off] : 0;
        __syncthreads();
        sm[tid] += tv;
        __syncthreads();
    }
    if (tid < NSCAN) partials[tid] = sm[tid] - v;
}

__global__ void scan3_kernel(int* __restrict__ rp, const int* __restrict__ partials,
                             int* __restrict__ cursor) {
    int tid = threadIdx.x;
    int base = blockIdx.x * SCAN_BLK + tid * 4;
    int off = partials[blockIdx.x];
#pragma unroll
    for (int i = 0; i < 4; i++) {
        int idx = base + i;
        if (idx < NN) {
            int val = rp[idx] + off;
            rp[idx] = val;
            cursor[idx] = val;
        }
    }
    if (blockIdx.x == 0 && tid == 0) rp[NN] = EE;
}

__global__ void fill_csr_kernel(const int* __restrict__ src, const int* __restrict__ dst,
                                int* __restrict__ cursor, int* __restrict__ csr) {
    int e = blockIdx.x * blockDim.x + threadIdx.x;
    if (e >= EE) return;
    int slot = atomicAdd(&cursor[dst[e]], 1);
    csr[slot] = src[e];
}

// ---------------- tf32 tensor-core GEMM, dis-scaled fp32 output ----------------
// t'[m] = ((op(A) @ B)[m] + rowvec) * dis[m]; op(A) optionally BN+ReLU per column.
template <int BN_T, bool APPLY_BN>
__global__ void __launch_bounds__(256, 2)
mma_gemm_kernel(const float* __restrict__ A, const float* __restrict__ B,
                const float* __restrict__ rowvec, const float* __restrict__ dis,
                const float* __restrict__ bn_a, const float* __restrict__ bn_b,
                float* __restrict__ Tout,
                int M, int Ncols, int K) {
    constexpr int BM = 128, BK = 32;
    constexpr int AS_STRIDE = BK + 4;
    constexpr int BS_STRIDE = BN_T + 8;
    __shared__ uint32_t As[BM * AS_STRIDE];
    __shared__ uint32_t Bs[BK * BS_STRIDE];

    const int tid = threadIdx.x;
    const int wid = tid >> 5, lane = tid & 31;
    const int gid = lane >> 2, tig = lane & 3;
    const int wm = wid & 3, wn = wid >> 2;
    constexpr int WM = 32, WN = BN_T / 2;
    constexpr int MT = WM / 16;
    constexpr int NT = WN / 8;
    const int m0 = blockIdx.y * BM, n0 = blockIdx.x * BN_T;

    float acc[MT][NT][4];
#pragma unroll
    for (int i = 0; i < MT; i++)
#pragma unroll
        for (int j = 0; j < NT; j++)
#pragma unroll
            for (int q = 0; q < 4; q++) acc[i][j][q] = 0.0f;

    for (int k0 = 0; k0 < K; k0 += BK) {
#pragma unroll
        for (int j = 0; j < (BM * BK) / (256 * 4); j++) {
            int idx = tid + j * 256;
            int r = idx >> 3, c4 = (idx & 7) * 4;
            int row = m0 + r;
            float4 v = make_float4(0.f, 0.f, 0.f, 0.f);
            if (row < M)
                v = *reinterpret_cast<const float4*>(&A[(size_t)row * K + k0 + c4]);
            if (APPLY_BN) {
                v.x = fmaxf(fmaf(v.x, bn_a[k0 + c4 + 0], bn_b[k0 + c4 + 0]), 0.f);
                v.y = fmaxf(fmaf(v.y, bn_a[k0 + c4 + 1], bn_b[k0 + c4 + 1]), 0.f);
                v.z = fmaxf(fmaf(v.z, bn_a[k0 + c4 + 2], bn_b[k0 + c4 + 2]), 0.f);
                v.w = fmaxf(fmaf(v.w, bn_a[k0 + c4 + 3], bn_b[k0 + c4 + 3]), 0.f);
            }
            uint4 u = make_uint4(f2tf32(v.x), f2tf32(v.y), f2tf32(v.z), f2tf32(v.w));
            *reinterpret_cast<uint4*>(&As[r * AS_STRIDE + c4]) = u;
        }
#pragma unroll
        for (int j = 0; j < (BK * BN_T) / (256 * 4); j++) {
            int idx = tid + j * 256;
            int kr = idx / (BN_T / 4), c4 = (idx % (BN_T / 4)) * 4;
            int col = n0 + c4;
            float4 v = make_float4(0.f, 0.f, 0.f, 0.f);
            if (col + 4 <= Ncols)
                v = *reinterpret_cast<const float4*>(&B[(size_t)(k0 + kr) * Ncols + col]);
            uint4 u = make_uint4(f2tf32(v.x), f2tf32(v.y), f2tf32(v.z), f2tf32(v.w));
            *reinterpret_cast<uint4*>(&Bs[kr * BS_STRIDE + c4]) = u;
        }
        __syncthreads();

#pragma unroll
        for (int k8 = 0; k8 < BK; k8 += 8) {
            uint32_t bf[NT][2];
#pragma unroll
            for (int nt = 0; nt < NT; nt++) {
                int ncol = wn * WN + nt * 8 + gid;
                bf[nt][0] = Bs[(k8 + tig) * BS_STRIDE + ncol];
                bf[nt][1] = Bs[(k8 + tig + 4) * BS_STRIDE + ncol];
            }
#pragma unroll
            for (int mt = 0; mt < MT; mt++) {
                int mrow = wm * WM + mt * 16 + gid;
                uint32_t a0 = As[mrow * AS_STRIDE + k8 + tig];
                uint32_t a1 = As[(mrow + 8) * AS_STRIDE + k8 + tig];
                uint32_t a2 = As[mrow * AS_STRIDE + k8 + tig + 4];
                uint32_t a3 = As[(mrow + 8) * AS_STRIDE + k8 + tig + 4];
#pragma unroll
                for (int nt = 0; nt < NT; nt++)
                    mma_tf32(acc[mt][nt][0], acc[mt][nt][1], acc[mt][nt][2], acc[mt][nt][3],
                             a0, a1, a2, a3, bf[nt][0], bf[nt][1]);
            }
        }
        __syncthreads();
    }

#pragma unroll
    for (int mt = 0; mt < MT; mt++) {
        int r0 = m0 + wm * WM + mt * 16 + gid;
        int r1 = r0 + 8;
        float d0 = (r0 < M) ? dis[r0] : 0.f;
        float d1 = (r1 < M) ? dis[r1] : 0.f;
#pragma unroll
        for (int nt = 0; nt < NT; nt++) {
            int col = n0 + wn * WN + nt * 8 + tig * 2;
            if (col + 2 > Ncols) continue;
            float2 rv = *reinterpret_cast<const float2*>(&rowvec[col]);
            if (r0 < M)
                *reinterpret_cast<float2*>(&Tout[(size_t)r0 * Ncols + col]) =
                    make_float2((acc[mt][nt][0] + rv.x) * d0, (acc[mt][nt][1] + rv.y) * d0);
            if (r1 < M)
                *reinterpret_cast<float2*>(&Tout[(size_t)r1 * Ncols + col]) =
                    make_float2((acc[mt][nt][2] + rv.x) * d1, (acc[mt][nt][3] + rv.y) * d1);
        }
    }
}

// ---------------- CSR gather aggregation (C=256, dis-scaled t) + fused BN stats ----------------
// agg[n] = dis[n] * (t'[n] + sum_src t'[src]) + bias   (edge coefficient factored out)
#define GATHER_G 16
__global__ void __launch_bounds__(256)
gather_wide_kernel(const int* __restrict__ rp, const int* __restrict__ csr,
                   const float* __restrict__ dis, const float* __restrict__ t,
                   const float* __restrict__ bias,
                   float* __restrict__ agg, float* __restrict__ stats) {
    int c = threadIdx.x;
    float b = bias[c];
    float s1 = 0.f, s2 = 0.f;
    int n0 = blockIdx.x * GATHER_G;
#pragma unroll 1
    for (int g = 0; g < GATHER_G; g++) {
        int n = n0 + g;
        if (n >= NN) break;
        float acc = t[(size_t)n * CH + c];  // self term (already dis-scaled)
        int e = rp[n], e1 = rp[n + 1];
        for (; e + 2 <= e1; e += 2) {
            int sa = csr[e];
            int sb = csr[e + 1];
            float va = t[(size_t)sa * CH + c];
            float vb = t[(size_t)sb * CH + c];
            acc += va + vb;
        }
        if (e < e1) {
            int sa = csr[e];
            acc += t[(size_t)sa * CH + c];
        }
        acc = fmaf(acc, dis[n], b);
        agg[(size_t)n * CH + c] = acc;
        s1 += acc;
        s2 += acc * acc;
    }
    atomicAdd(&stats[c], s1);
    atomicAdd(&stats[CH + c], s2);
}

// ---------------- BN finalize (also initializes z = vnb for the VN matvec) ----------------
__global__ void finalize_stats_kernel(const float* __restrict__ stats,
                                      const float* __restrict__ g, const float* __restrict__ bv,
                                      const float* __restrict__ vnb,
                                      float* __restrict__ bn_a, float* __restrict__ bn_b,
                                      float* __restrict__ z) {
    int c = threadIdx.x;
    float m = stats[c] * (1.0f / (float)NN);
    float v = stats[CH + c] * (1.0f / (float)NN) - m * m;
    float a = rsqrtf(v + BN_EPS) * g[c];
    bn_a[c] = a;
    bn_b[c] = bv[c] - m * a;
    z[c] = vnb[c];
}

__global__ void pool_kernel(const float* __restrict__ agg,
                            const float* __restrict__ bn_a, const float* __restrict__ bn_b,
                            float* __restrict__ pool) {
    int c = threadIdx.x;
    float a = bn_a[c], b = bn_b[c];
    float ps = 0.f;
    for (int r = blockIdx.x; r < NN; r += gridDim.x)
        ps += fmaxf(fmaf(agg[(size_t)r * CH + c], a, b), 0.f);
    atomicAdd(&pool[c], ps);
}

// ---------------- virtual-node MLP ----------------
// z[c] += sum over 32-k slice of (pool[k]+vx_prev[k]) * W[k][c]   (grid = 8 k-splits)
__global__ void vn_matvec_kernel(const float* __restrict__ pool, const float* __restrict__ vx_prev,
                                 const float* __restrict__ W, float* __restrict__ z, int cols) {
    __shared__ float ss[32];
    int c = threadIdx.x;
    int kb = blockIdx.x * 32;
    if (c < 32) ss[c] = pool[kb + c] + vx_prev[kb + c];
    __syncthreads();
    if (c < cols) {
        float acc = 0.f;
#pragma unroll
        for (int k = 0; k < 32; k++) acc = fmaf(ss[k], W[(size_t)(kb + k) * cols + c], acc);
        atomicAdd(&z[c], acc);
    }
}

// LayerNorm+ReLU; re-zeros stats/pool/rowvec for the next layer
__global__ void vn_ln_kernel(const float* __restrict__ z,
                             const float* __restrict__ lng, const float* __restrict__ lnb,
                             float* __restrict__ vx_out, float* __restrict__ rowvec,
                             float* __restrict__ stats, float* __restrict__ pool) {
    __shared__ float red[CH];
    int c = threadIdx.x;
    float zv = z[c];
    red[c] = zv;
    __syncthreads();
    for (int off = CH / 2; off; off >>= 1) {
        if (c < off) red[c] += red[c + off];
        __syncthreads();
    }
    float mu = red[0] * (1.0f / (float)CH);
    __syncthreads();
    float d = zv - mu;
    red[c] = d * d;
    __syncthreads();
    for (int off = CH / 2; off; off >>= 1) {
        if (c < off) red[c] += red[c + off];
        __syncthreads();
    }
    float var = red[0] * (1.0f / (float)CH);
    vx_out[c] = fmaxf(fmaf(d * rsqrtf(var + BN_EPS), lng[c], lnb[c]), 0.f);
    rowvec[c] = 0.f;
    stats[c] = 0.f;
    stats[CH + c] = 0.f;
    pool[c] = 0.f;
}

__global__ void rowvec_matvec_kernel(const float* __restrict__ vx, const float* __restrict__ W,
                                     float* __restrict__ rowvec, int cols) {
    __shared__ float ss[32];
    int c = threadIdx.x;
    int kb = blockIdx.x * 32;
    if (c < 32) ss[c] = vx[kb + c];
    __syncthreads();
    if (c < cols) {
        float acc = 0.f;
#pragma unroll
        for (int k = 0; k < 32; k++) acc = fmaf(ss[k], W[(size_t)(kb + k) * cols + c], acc);
        atomicAdd(&rowvec[c], acc);
    }
}

// ---------------- final layer: CSR gather (C=40, dis-scaled t) + log_softmax ----------------
__global__ void __launch_bounds__(256)
gather_out_kernel(const int* __restrict__ rp, const int* __restrict__ csr,
                  const float* __restrict__ dis, const float* __restrict__ t,
                  const float* __restrict__ bias, float* __restrict__ out) {
    int warp = threadIdx.x >> 5;
    int lane = threadIdx.x & 31;
    int n = blockIdx.x * 8 + warp;
    if (n >= NN) return;

    const float* tn = t + (size_t)n * COUT;
    float acc0 = tn[lane];
    float acc1 = (lane < COUT - 32) ? tn[32 + lane] : 0.f;

    int e = rp[n], e1 = rp[n + 1];
    for (; e + 2 <= e1; e += 2) {
        int sa = csr[e];
        int sb = csr[e + 1];
        const float* ta = t + (size_t)sa * COUT;
        const float* tb = t + (size_t)sb * COUT;
        acc0 += ta[lane] + tb[lane];
        if (lane < COUT - 32) acc1 += ta[32 + lane] + tb[32 + lane];
    }
    if (e < e1) {
        int sa = csr[e];
        const float* ta = t + (size_t)sa * COUT;
        acc0 += ta[lane];
        if (lane < COUT - 32) acc1 += ta[32 + lane];
    }

    float dn = dis[n];
    acc0 = fmaf(acc0, dn, bias[lane]);
    acc1 = (lane < COUT - 32) ? fmaf(acc1, dn, bias[32 + lane]) : -1e30f;

    float m = fmaxf(acc0, acc1);
#pragma unroll
    for (int off = 16; off; off >>= 1) m = fmaxf(m, __shfl_xor_sync(0xffffffffu, m, off));
    float sum = expf(acc0 - m) + ((lane < COUT - 32) ? expf(acc1 - m) : 0.f);
#pragma unroll
    for (int off = 16; off; off >>= 1) sum += __shfl_xor_sync(0xffffffffu, sum, off);
    float l = m + logf(sum);
    out[(size_t)n * COUT + lane] = acc0 - l;
    if (lane < COUT - 32) out[(size_t)n * COUT + 32 + lane] = acc1 - l;
}

// ---------------- driver ----------------
extern "C" void kernel_launch(void* const* d_in, const int* in_sizes, int n_in,
                              void* d_out, int out_size) {
    const float* x      = (const float*)d_in[0];
    const int*   ei     = (const int*)d_in[1];
    const float* W0     = (const float*)d_in[2];
    const float* b0     = (const float*)d_in[3];
    const float* W1     = (const float*)d_in[4];
    const float* b1     = (const float*)d_in[5];
    const float* W2     = (const float*)d_in[6];
    const float* b2     = (const float*)d_in[7];
    const float* bn_g0  = (const float*)d_in[8];
    const float* bn_b0  = (const float*)d_in[9];
    const float* bn_g1  = (const float*)d_in[10];
    const float* bn_b1  = (const float*)d_in[11];
    const float* vn_emb = (const float*)d_in[12];
    const float* vn_W0  = (const float*)d_in[13];
    const float* vn_b0  = (const float*)d_in[14];
    const float* ln_g0  = (const float*)d_in[15];
    const float* ln_b0  = (const float*)d_in[16];
    const float* vn_W1  = (const float*)d_in[17];
    const float* vn_b1  = (const float*)d_in[18];
    const float* ln_g1  = (const float*)d_in[19];
    const float* ln_b1  = (const float*)d_in[20];
    float* out = (float*)d_out;

    const int* src = ei;
    const int* dst = ei + EE;

    float *t, *agg, *dis, *stats, *bn_a, *bn_b, *pool, *vx, *rowvec, *z;
    int *deg, *rowptr, *cursor, *csr, *partials;
    cudaGetSymbolAddress((void**)&t, g_t);
    cudaGetSymbolAddress((void**)&agg, g_agg);
    cudaGetSymbolAddress((void**)&dis, g_dis);
    cudaGetSymbolAddress((void**)&deg, g_deg);
    cudaGetSymbolAddress((void**)&rowptr, g_rowptr);
    cudaGetSymbolAddress((void**)&cursor, g_cursor);
    cudaGetSymbolAddress((void**)&csr, g_csr_src);
    cudaGetSymbolAddress((void**)&partials, g_partials);
    cudaGetSymbolAddress((void**)&stats, g_stats);
    cudaGetSymbolAddress((void**)&bn_a, g_bn_a);
    cudaGetSymbolAddress((void**)&bn_b, g_bn_b);
    cudaGetSymbolAddress((void**)&pool, g_pool);
    cudaGetSymbolAddress((void**)&vx, g_vx);
    cudaGetSymbolAddress((void**)&rowvec, g_rowvec);
    cudaGetSymbolAddress((void**)&z, g_z);

    const int T = 256;
    const int STAT_BLOCKS = 1024;
    dim3 gemm_wide(CH / 128, (NN + 127) / 128);
    dim3 gemm_narrow(1, (NN + 127) / 128);
    int gather_blocks = (NN + GATHER_G - 1) / GATHER_G;

    // ---- CSR build + normalization ----
    zero_deg_kernel<<<(NN + T - 1) / T, T>>>(deg, stats, pool, rowvec);
    count_deg_kernel<<<(EE + T - 1) / T, T>>>(dst, deg);
    compute_dis_kernel<<<(NN + T - 1) / T, T>>>(deg, dis);
    scan1_kernel<<<NSCAN, 256>>>(deg, rowptr, partials);
    scan2_kernel<<<1, 128>>>(partials);
    scan3_kernel<<<NSCAN, 256>>>(rowptr, partials, cursor);
    fill_csr_kernel<<<(EE + T - 1) / T, T>>>(src, dst, cursor, csr);

    // ---- layer 0 ----
    rowvec_matvec_kernel<<<8, T>>>(vn_emb, W0, rowvec, CH);
    mma_gemm_kernel<128, false><<<gemm_wide, T>>>(x, W0, rowvec, dis,
                                                  nullptr, nullptr, t, NN, CH, CH);
    gather_wide_kernel<<<gather_blocks, T>>>(rowptr, csr, dis, t, b0, agg, stats);
    finalize_stats_kernel<<<1, T>>>(stats, bn_g0, bn_b0, vn_b0, bn_a, bn_b, z);
    pool_kernel<<<STAT_BLOCKS, T>>>(agg, bn_a, bn_b, pool);
    vn_matvec_kernel<<<8, T>>>(pool, vn_emb, vn_W0, z, CH);
    vn_ln_kernel<<<1, T>>>(z, ln_g0, ln_b0, vx, rowvec, stats, pool);
    rowvec_matvec_kernel<<<8, T>>>(vx, W1, rowvec, CH);

    // ---- layer 1 ----
    mma_gemm_kernel<128, true><<<gemm_wide, T>>>(agg, W1, rowvec, dis,
                                                 bn_a, bn_b, t, NN, CH, CH);
    gather_wide_kernel<<<gather_blocks, T>>>(rowptr, csr, dis, t, b1, agg, stats);
    finalize_stats_kernel<<<1, T>>>(stats, bn_g1, bn_b1, vn_b1, bn_a, bn_b, z);
    pool_kernel<<<STAT_BLOCKS, T>>>(agg, bn_a, bn_b, pool);
    vn_matvec_kernel<<<8, T>>>(pool, vx, vn_W1, z, CH);
    vn_ln_kernel<<<1, T>>>(z, ln_g1, ln_b1, vx, rowvec, stats, pool);
    rowvec_matvec_kernel<<<8, T>>>(vx, W2, rowvec, COUT);

    // ---- layer 2 (output, fused gather + log_softmax) ----
    mma_gemm_kernel<64, true><<<gemm_narrow, T>>>(agg, W2, rowvec, dis,
                                                  bn_a, bn_b, t, NN, COUT, CH);
    gather_out_kernel<<<(NN + 7) / 8, T>>>(rowptr, csr, dis, t, b2, out);
}

// round 13
// speedup vs baseline: 1.3193x; 1.0503x over previous
#include <cuda_runtime.h>
#include <math.h>
#include <stddef.h>
#include <stdint.h>

#define NN   100000
#define EE   800000
#define CH   256
#define COUT 40
#define BN_EPS 1e-5f
#define SCAN_BLK 1024
#define NSCAN ((NN + SCAN_BLK - 1) / SCAN_BLK)  // 98

// ---------------- scratch (device globals) ----------------
__device__ float g_t[(size_t)NN * CH];    // GEMM output, pre-scaled by dis[row]
__device__ float g_agg[(size_t)NN * CH];  // aggregated (GCN output pre-BN)
__device__ float g_dis[NN];
__device__ float g_wsum[NN];
__device__ int   g_deg[NN];
__device__ int   g_rowptr[NN + 1];
__device__ int   g_cursor[NN];
__device__ int   g_csr_src[EE];
__device__ int   g_partials[256];
__device__ float g_stats[2 * CH];
__device__ float g_bn_a[CH];
__device__ float g_bn_b[CH];
__device__ float g_pool[CH];
__device__ float g_vx[CH];
__device__ float g_rowvec[CH];
__device__ float g_z[CH];

// ---------------- helpers ----------------
__device__ __forceinline__ uint32_t f2tf32(float x) {
    uint32_t u;
    asm("cvt.rna.tf32.f32 %0, %1;" : "=r"(u) : "f"(x));
    return u;
}

__device__ __forceinline__ void mma_tf32(float& c0, float& c1, float& c2, float& c3,
                                         uint32_t a0, uint32_t a1, uint32_t a2, uint32_t a3,
                                         uint32_t b0, uint32_t b1) {
    asm volatile("mma.sync.aligned.m16n8k8.row.col.f32.tf32.tf32.f32 "
                 "{%0,%1,%2,%3}, {%4,%5,%6,%7}, {%8,%9}, {%0,%1,%2,%3};"
                 : "+f"(c0), "+f"(c1), "+f"(c2), "+f"(c3)
                 : "r"(a0), "r"(a1), "r"(a2), "r"(a3), "r"(b0), "r"(b1));
}

// ---------------- degree / init ----------------
__global__ void zero_deg_kernel(int* __restrict__ deg, float* __restrict__ stats,
                                float* __restrict__ pool, float* __restrict__ rowvec) {
    int i = blockIdx.x * blockDim.x + threadIdx.x;
    if (i < NN) deg[i] = 0;
    if (i < CH) {
        stats[i] = 0.f;
        stats[i + CH] = 0.f;
        pool[i] = 0.f;
        rowvec[i] = 0.f;
    }
}
__global__ void count_deg_kernel(const int* __restrict__ dst, int* __restrict__ deg) {
    int e = blockIdx.x * blockDim.x + threadIdx.x;
    if (e < EE) atomicAdd(&deg[dst[e]], 1);
}
__global__ void compute_dis_kernel(const int* __restrict__ deg, float* __restrict__ dis) {
    int i = blockIdx.x * blockDim.x + threadIdx.x;
    if (i < NN) dis[i] = rsqrtf((float)deg[i] + 1.0f);
}

// wsum[n] = dis[n] * (dis[n] + sum_{e into n} dis[src])
__global__ void compute_wsum_kernel(const int* __restrict__ rp, const int* __restrict__ csr,
                                    const float* __restrict__ dis, float* __restrict__ wsum) {
    int n = blockIdx.x * blockDim.x + threadIdx.x;
    if (n >= NN) return;
    float dn = dis[n];
    float s = dn;
    int e1 = rp[n + 1];
    for (int e = rp[n]; e < e1; e++) s += dis[csr[e]];
    wsum[n] = dn * s;
}

// ---------------- exclusive scan (3 phases) ----------------
__global__ void scan1_kernel(const int* __restrict__ deg, int* __restrict__ rp,
                             int* __restrict__ partials) {
    __shared__ int sm[256];
    int tid = threadIdx.x;
    int base = blockIdx.x * SCAN_BLK + tid * 4;
    int v[4];
    int s = 0;
#pragma unroll
    for (int i = 0; i < 4; i++) {
        v[i] = (base + i < NN) ? deg[base + i] : 0;
        s += v[i];
    }
    sm[tid] = s;
    __syncthreads();
#pragma unroll
    for (int off = 1; off < 256; off <<= 1) {
        int tv = (tid >= off) ? sm[tid - off] : 0;
        __syncthreads();
        sm[tid] += tv;
        __syncthreads();
    }
    int excl = sm[tid] - s;
    if (tid == 255) partials[blockIdx.x] = sm[255];
    int run = excl;
#pragma unroll
    for (int i = 0; i < 4; i++) {
        if (base + i < NN) rp[base + i] = run;
        run += v[i];
    }
}

__global__ void scan2_kernel(int* __restrict__ partials) {
    __shared__ int sm[128];
    int tid = threadIdx.x;
    int v = (tid < NSCAN) ? partials[tid] : 0;
    sm[tid] = v;
    __syncthreads();
#pragma unroll
    for (int off = 1; off < 128; off <<= 1) {
        int tv = (tid >= off) ? sm[tid - off] : 0;
        __syncthreads();
        sm[tid] += tv;
        __syncthreads();
    }
    if (tid < NSCAN) partials[tid] = sm[tid] - v;
}

__global__ void scan3_kernel(int* __restrict__ rp, const int* __restrict__ partials,
                             int* __restrict__ cursor) {
    int tid = threadIdx.x;
    int base = blockIdx.x * SCAN_BLK + tid * 4;
    int off = partials[blockIdx.x];
#pragma unroll
    for (int i = 0; i < 4; i++) {
        int idx = base + i;
        if (idx < NN) {
            int val = rp[idx] + off;
            rp[idx] = val;
            cursor[idx] = val;
        }
    }
    if (blockIdx.x == 0 && tid == 0) rp[NN] = EE;
}

__global__ void fill_csr_kernel(const int* __restrict__ src, const int* __restrict__ dst,
                                int* __restrict__ cursor, int* __restrict__ csr) {
    int e = blockIdx.x * blockDim.x + threadIdx.x;
    if (e >= EE) return;
    int slot = atomicAdd(&cursor[dst[e]], 1);
    csr[slot] = src[e];
}

// ---------------- tf32 tensor-core GEMM, dis-scaled fp32 output ----------------
// t'[m] = (op(A) @ B)[m] * dis[m]; op(A) optionally BN+ReLU per column.
template <int BN_T, bool APPLY_BN>
__global__ void __launch_bounds__(256, 2)
mma_gemm_kernel(const float* __restrict__ A, const float* __restrict__ B,
                const float* __restrict__ dis,
                const float* __restrict__ bn_a, const float* __restrict__ bn_b,
                float* __restrict__ Tout,
                int M, int Ncols, int K) {
    constexpr int BM = 128, BK = 32;
    constexpr int AS_STRIDE = BK + 4;
    constexpr int BS_STRIDE = BN_T + 8;
    constexpr int B_ELEMS4 = BK * BN_T / 4;  // float4 slots in B tile
    __shared__ uint32_t As[BM * AS_STRIDE];
    __shared__ uint32_t Bs[BK * BS_STRIDE];

    const int tid = threadIdx.x;
    const int wid = tid >> 5, lane = tid & 31;
    const int gid = lane >> 2, tig = lane & 3;
    const int wm = wid & 3, wn = wid >> 2;
    constexpr int WM = 32, WN = BN_T / 2;
    constexpr int MT = WM / 16;
    constexpr int NT = WN / 8;
    const int m0 = blockIdx.y * BM, n0 = blockIdx.x * BN_T;

    float acc[MT][NT][4];
#pragma unroll
    for (int i = 0; i < MT; i++)
#pragma unroll
        for (int j = 0; j < NT; j++)
#pragma unroll
            for (int q = 0; q < 4; q++) acc[i][j][q] = 0.0f;

    for (int k0 = 0; k0 < K; k0 += BK) {
#pragma unroll
        for (int j = 0; j < (BM * BK) / (256 * 4); j++) {
            int idx = tid + j * 256;
            int r = idx >> 3, c4 = (idx & 7) * 4;
            int row = m0 + r;
            float4 v = make_float4(0.f, 0.f, 0.f, 0.f);
            if (row < M)
                v = *reinterpret_cast<const float4*>(&A[(size_t)row * K + k0 + c4]);
            if (APPLY_BN) {
                v.x = fmaxf(fmaf(v.x, bn_a[k0 + c4 + 0], bn_b[k0 + c4 + 0]), 0.f);
                v.y = fmaxf(fmaf(v.y, bn_a[k0 + c4 + 1], bn_b[k0 + c4 + 1]), 0.f);
                v.z = fmaxf(fmaf(v.z, bn_a[k0 + c4 + 2], bn_b[k0 + c4 + 2]), 0.f);
                v.w = fmaxf(fmaf(v.w, bn_a[k0 + c4 + 3], bn_b[k0 + c4 + 3]), 0.f);
            }
            uint4 u = make_uint4(f2tf32(v.x), f2tf32(v.y), f2tf32(v.z), f2tf32(v.w));
            *reinterpret_cast<uint4*>(&As[r * AS_STRIDE + c4]) = u;
        }
#pragma unroll
        for (int j = 0; j < (B_ELEMS4 + 255) / 256; j++) {
            int idx = tid + j * 256;
            if (idx < B_ELEMS4) {
                int kr = idx / (BN_T / 4), c4 = (idx % (BN_T / 4)) * 4;
                int col = n0 + c4;
                float4 v = make_float4(0.f, 0.f, 0.f, 0.f);
                if (col + 4 <= Ncols)
                    v = *reinterpret_cast<const float4*>(&B[(size_t)(k0 + kr) * Ncols + col]);
                uint4 u = make_uint4(f2tf32(v.x), f2tf32(v.y), f2tf32(v.z), f2tf32(v.w));
                *reinterpret_cast<uint4*>(&Bs[kr * BS_STRIDE + c4]) = u;
            }
        }
        __syncthreads();

#pragma unroll
        for (int k8 = 0; k8 < BK; k8 += 8) {
            uint32_t bf[NT][2];
#pragma unroll
            for (int nt = 0; nt < NT; nt++) {
                int ncol = wn * WN + nt * 8 + gid;
                bf[nt][0] = Bs[(k8 + tig) * BS_STRIDE + ncol];
                bf[nt][1] = Bs[(k8 + tig + 4) * BS_STRIDE + ncol];
            }
#pragma unroll
            for (int mt = 0; mt < MT; mt++) {
                int mrow = wm * WM + mt * 16 + gid;
                uint32_t a0 = As[mrow * AS_STRIDE + k8 + tig];
                uint32_t a1 = As[(mrow + 8) * AS_STRIDE + k8 + tig];
                uint32_t a2 = As[mrow * AS_STRIDE + k8 + tig + 4];
                uint32_t a3 = As[(mrow + 8) * AS_STRIDE + k8 + tig + 4];
#pragma unroll
                for (int nt = 0; nt < NT; nt++)
                    mma_tf32(acc[mt][nt][0], acc[mt][nt][1], acc[mt][nt][2], acc[mt][nt][3],
                             a0, a1, a2, a3, bf[nt][0], bf[nt][1]);
            }
        }
        __syncthreads();
    }

#pragma unroll
    for (int mt = 0; mt < MT; mt++) {
        int r0 = m0 + wm * WM + mt * 16 + gid;
        int r1 = r0 + 8;
        float d0 = (r0 < M) ? dis[r0] : 0.f;
        float d1 = (r1 < M) ? dis[r1] : 0.f;
#pragma unroll
        for (int nt = 0; nt < NT; nt++) {
            int col = n0 + wn * WN + nt * 8 + tig * 2;
            if (col + 2 > Ncols) continue;
            if (r0 < M)
                *reinterpret_cast<float2*>(&Tout[(size_t)r0 * Ncols + col]) =
                    make_float2(acc[mt][nt][0] * d0, acc[mt][nt][1] * d0);
            if (r1 < M)
                *reinterpret_cast<float2*>(&Tout[(size_t)r1 * Ncols + col]) =
                    make_float2(acc[mt][nt][2] * d1, acc[mt][nt][3] * d1);
        }
    }
}

// ---------------- CSR gather aggregation (C=256, dis-scaled t) + fused BN stats ----------------
// agg[n] = dis[n]*(t'[n] + sum_src t'[src]) + rowvec[c]*wsum[n] + bias[c]
#define GATHER_G 16
__global__ void __launch_bounds__(256)
gather_wide_kernel(const int* __restrict__ rp, const int* __restrict__ csr,
                   const float* __restrict__ dis, const float* __restrict__ wsum,
                   const float* __restrict__ t,
                   const float* __restrict__ rowvec, const float* __restrict__ bias,
                   float* __restrict__ agg, float* __restrict__ stats) {
    int c = threadIdx.x;
    float b = bias[c];
    float rv = rowvec[c];
    float s1 = 0.f, s2 = 0.f;
    int n0 = blockIdx.x * GATHER_G;
#pragma unroll 1
    for (int g = 0; g < GATHER_G; g++) {
        int n = n0 + g;
        if (n >= NN) break;
        float acc = t[(size_t)n * CH + c];  // self term (already dis-scaled)
        int e = rp[n], e1 = rp[n + 1];
        for (; e + 2 <= e1; e += 2) {
            int sa = csr[e];
            int sb = csr[e + 1];
            float va = t[(size_t)sa * CH + c];
            float vb = t[(size_t)sb * CH + c];
            acc += va + vb;
        }
        if (e < e1) {
            int sa = csr[e];
            acc += t[(size_t)sa * CH + c];
        }
        acc = fmaf(acc, dis[n], fmaf(rv, wsum[n], b));
        agg[(size_t)n * CH + c] = acc;
        s1 += acc;
        s2 += acc * acc;
    }
    atomicAdd(&stats[c], s1);
    atomicAdd(&stats[CH + c], s2);
}

// ---------------- BN finalize (also initializes z = vnb for the VN matvec) ----------------
__global__ void finalize_stats_kernel(const float* __restrict__ stats,
                                      const float* __restrict__ g, const float* __restrict__ bv,
                                      const float* __restrict__ vnb,
                                      float* __restrict__ bn_a, float* __restrict__ bn_b,
                                      float* __restrict__ z) {
    int c = threadIdx.x;
    float m = stats[c] * (1.0f / (float)NN);
    float v = stats[CH + c] * (1.0f / (float)NN) - m * m;
    float a = rsqrtf(v + BN_EPS) * g[c];
    bn_a[c] = a;
    bn_b[c] = bv[c] - m * a;
    z[c] = vnb[c];
}

__global__ void pool_kernel(const float* __restrict__ agg,
                            const float* __restrict__ bn_a, const float* __restrict__ bn_b,
                            float* __restrict__ pool) {
    int c = threadIdx.x;
    float a = bn_a[c], b = bn_b[c];
    float ps = 0.f;
    for (int r = blockIdx.x; r < NN; r += gridDim.x)
        ps += fmaxf(fmaf(agg[(size_t)r * CH + c], a, b), 0.f);
    atomicAdd(&pool[c], ps);
}

// ---------------- virtual-node MLP ----------------
__global__ void vn_matvec_kernel(const float* __restrict__ pool, const float* __restrict__ vx_prev,
                                 const float* __restrict__ W, float* __restrict__ z, int cols) {
    __shared__ float ss[32];
    int c = threadIdx.x;
    int kb = blockIdx.x * 32;
    if (c < 32) ss[c] = pool[kb + c] + vx_prev[kb + c];
    __syncthreads();
    if (c < cols) {
        float acc = 0.f;
#pragma unroll
        for (int k = 0; k < 32; k++) acc = fmaf(ss[k], W[(size_t)(kb + k) * cols + c], acc);
        atomicAdd(&z[c], acc);
    }
}

// LayerNorm+ReLU; re-zeros stats/pool/rowvec for the next layer
__global__ void vn_ln_kernel(const float* __restrict__ z,
                             const float* __restrict__ lng, const float* __restrict__ lnb,
                             float* __restrict__ vx_out, float* __restrict__ rowvec,
                             float* __restrict__ stats, float* __restrict__ pool) {
    __shared__ float red[CH];
    int c = threadIdx.x;
    float zv = z[c];
    red[c] = zv;
    __syncthreads();
    for (int off = CH / 2; off; off >>= 1) {
        if (c < off) red[c] += red[c + off];
        __syncthreads();
    }
    float mu = red[0] * (1.0f / (float)CH);
    __syncthreads();
    float d = zv - mu;
    red[c] = d * d;
    __syncthreads();
    for (int off = CH / 2; off; off >>= 1) {
        if (c < off) red[c] += red[c + off];
        __syncthreads();
    }
    float var = red[0] * (1.0f / (float)CH);
    vx_out[c] = fmaxf(fmaf(d * rsqrtf(var + BN_EPS), lng[c], lnb[c]), 0.f);
    rowvec[c] = 0.f;
    stats[c] = 0.f;
    stats[CH + c] = 0.f;
    pool[c] = 0.f;
}

__global__ void rowvec_matvec_kernel(const float* __restrict__ vx, const float* __restrict__ W,
                                     float* __restrict__ rowvec, int cols) {
    __shared__ float ss[32];
    int c = threadIdx.x;
    int kb = blockIdx.x * 32;
    if (c < 32) ss[c] = vx[kb + c];
    __syncthreads();
    if (c < cols) {
        float acc = 0.f;
#pragma unroll
        for (int k = 0; k < 32; k++) acc = fmaf(ss[k], W[(size_t)(kb + k) * cols + c], acc);
        atomicAdd(&rowvec[c], acc);
    }
}

// ---------------- final layer: CSR gather (C=40, dis-scaled t) + log_softmax ----------------
__global__ void __launch_bounds__(256)
gather_out_kernel(const int* __restrict__ rp, const int* __restrict__ csr,
                  const float* __restrict__ dis, const float* __restrict__ wsum,
                  const float* __restrict__ t,
                  const float* __restrict__ rowvec, const float* __restrict__ bias,
                  float* __restrict__ out) {
    int warp = threadIdx.x >> 5;
    int lane = threadIdx.x & 31;
    int n = blockIdx.x * 8 + warp;
    if (n >= NN) return;

    const float* tn = t + (size_t)n * COUT;
    float acc0 = tn[lane];
    float acc1 = (lane < COUT - 32) ? tn[32 + lane] : 0.f;

    int e = rp[n], e1 = rp[n + 1];
    for (; e + 2 <= e1; e += 2) {
        int sa = csr[e];
        int sb = csr[e + 1];
        const float* ta = t + (size_t)sa * COUT;
        const float* tb = t + (size_t)sb * COUT;
        acc0 += ta[lane] + tb[lane];
        if (lane < COUT - 32) acc1 += ta[32 + lane] + tb[32 + lane];
    }
    if (e < e1) {
        int sa = csr[e];
        const float* ta = t + (size_t)sa * COUT;
        acc0 += ta[lane];
        if (lane < COUT - 32) acc1 += ta[32 + lane];
    }

    float dn = dis[n];
    float ws = wsum[n];
    acc0 = fmaf(acc0, dn, fmaf(rowvec[lane], ws, bias[lane]));
    acc1 = (lane < COUT - 32)
               ? fmaf(acc1, dn, fmaf(rowvec[32 + lane], ws, bias[32 + lane]))
               : -1e30f;

    float m = fmaxf(acc0, acc1);
#pragma unroll
    for (int off = 16; off; off >>= 1) m = fmaxf(m, __shfl_xor_sync(0xffffffffu, m, off));
    float sum = expf(acc0 - m) + ((lane < COUT - 32) ? expf(acc1 - m) : 0.f);
#pragma unroll
    for (int off = 16; off; off >>= 1) sum += __shfl_xor_sync(0xffffffffu, sum, off);
    float l = m + logf(sum);
    out[(size_t)n * COUT + lane] = acc0 - l;
    if (lane < COUT - 32) out[(size_t)n * COUT + 32 + lane] = acc1 - l;
}

// ---------------- driver ----------------
extern "C" void kernel_launch(void* const* d_in, const int* in_sizes, int n_in,
                              void* d_out, int out_size) {
    const float* x      = (const float*)d_in[0];
    const int*   ei     = (const int*)d_in[1];
    const float* W0     = (const float*)d_in[2];
    const float* b0     = (const float*)d_in[3];
    const float* W1     = (const float*)d_in[4];
    const float* b1     = (const float*)d_in[5];
    const float* W2     = (const float*)d_in[6];
    const float* b2     = (const float*)d_in[7];
    const float* bn_g0  = (const float*)d_in[8];
    const float* bn_b0  = (const float*)d_in[9];
    const float* bn_g1  = (const float*)d_in[10];
    const float* bn_b1  = (const float*)d_in[11];
    const float* vn_emb = (const float*)d_in[12];
    const float* vn_W0  = (const float*)d_in[13];
    const float* vn_b0  = (const float*)d_in[14];
    const float* ln_g0  = (const float*)d_in[15];
    const float* ln_b0  = (const float*)d_in[16];
    const float* vn_W1  = (const float*)d_in[17];
    const float* vn_b1  = (const float*)d_in[18];
    const float* ln_g1  = (const float*)d_in[19];
    const float* ln_b1  = (const float*)d_in[20];
    float* out = (float*)d_out;

    const int* src = ei;
    const int* dst = ei + EE;

    float *t, *agg, *dis, *wsum, *stats, *bn_a, *bn_b, *pool, *vx, *rowvec, *z;
    int *deg, *rowptr, *cursor, *csr, *partials;
    cudaGetSymbolAddress((void**)&t, g_t);
    cudaGetSymbolAddress((void**)&agg, g_agg);
    cudaGetSymbolAddress((void**)&dis, g_dis);
    cudaGetSymbolAddress((void**)&wsum, g_wsum);
    cudaGetSymbolAddress((void**)&deg, g_deg);
    cudaGetSymbolAddress((void**)&rowptr, g_rowptr);
    cudaGetSymbolAddress((void**)&cursor, g_cursor);
    cudaGetSymbolAddress((void**)&csr, g_csr_src);
    cudaGetSymbolAddress((void**)&partials, g_partials);
    cudaGetSymbolAddress((void**)&stats, g_stats);
    cudaGetSymbolAddress((void**)&bn_a, g_bn_a);
    cudaGetSymbolAddress((void**)&bn_b, g_bn_b);
    cudaGetSymbolAddress((void**)&pool, g_pool);
    cudaGetSymbolAddress((void**)&vx, g_vx);
    cudaGetSymbolAddress((void**)&rowvec, g_rowvec);
    cudaGetSymbolAddress((void**)&z, g_z);

    const int T = 256;
    const int STAT_BLOCKS = 1024;
    dim3 gemm_wide(CH / 128, (NN + 127) / 128);
    dim3 gemm_narrow(1, (NN + 127) / 128);
    int gather_blocks = (NN + GATHER_G - 1) / GATHER_G;

    // ---- prologue; wide GEMM placed at launch #4 so ncu (-s3/-c1) captures it ----
    zero_deg_kernel<<<(NN + T - 1) / T, T>>>(deg, stats, pool, rowvec);       // 1
    count_deg_kernel<<<(EE + T - 1) / T, T>>>(dst, deg);                      // 2
    compute_dis_kernel<<<(NN + T - 1) / T, T>>>(deg, dis);                    // 3
    mma_gemm_kernel<128, false><<<gemm_wide, T>>>(x, W0, dis,                 // 4
                                                  nullptr, nullptr, t, NN, CH, CH);
    rowvec_matvec_kernel<<<8, T>>>(vn_emb, W0, rowvec, CH);                   // 5
    scan1_kernel<<<NSCAN, 256>>>(deg, rowptr, partials);                      // 6
    scan2_kernel<<<1, 128>>>(partials);                                       // 7
    scan3_kernel<<<NSCAN, 256>>>(rowptr, partials, cursor);                   // 8
    fill_csr_kernel<<<(EE + T - 1) / T, T>>>(src, dst, cursor, csr);          // 9
    compute_wsum_kernel<<<(NN + T - 1) / T, T>>>(rowptr, csr, dis, wsum);     // 10

    // ---- layer 0 ----
    gather_wide_kernel<<<gather_blocks, T>>>(rowptr, csr, dis, wsum, t, rowvec, b0, agg, stats);
    finalize_stats_kernel<<<1, T>>>(stats, bn_g0, bn_b0, vn_b0, bn_a, bn_b, z);
    pool_kernel<<<STAT_BLOCKS, T>>>(agg, bn_a, bn_b, pool);
    vn_matvec_kernel<<<8, T>>>(pool, vn_emb, vn_W0, z, CH);
    vn_ln_kernel<<<1, T>>>(z, ln_g0, ln_b0, vx, rowvec, stats, pool);
    rowvec_matvec_kernel<<<8, T>>>(vx, W1, rowvec, CH);

    // ---- layer 1 ----
    mma_gemm_kernel<128, true><<<gemm_wide, T>>>(agg, W1, dis, bn_a, bn_b, t, NN, CH, CH);
    gather_wide_kernel<<<gather_blocks, T>>>(rowptr, csr, dis, wsum, t, rowvec, b1, agg, stats);
    finalize_stats_kernel<<<1, T>>>(stats, bn_g1, bn_b1, vn_b1, bn_a, bn_b, z);
    pool_kernel<<<STAT_BLOCKS, T>>>(agg, bn_a, bn_b, pool);
    vn_matvec_kernel<<<8, T>>>(pool, vx, vn_W1, z, CH);
    vn_ln_kernel<<<1, T>>>(z, ln_g1, ln_b1, vx, rowvec, stats, pool);
    rowvec_matvec_kernel<<<8, T>>>(vx, W2, rowvec, COUT);

    // ---- layer 2 (output, 48-col tile over 40 cols, fused gather + log_softmax) ----
    mma_gemm_kernel<48, true><<<gemm_narrow, T>>>(agg, W2, dis, bn_a, bn_b, t, NN, COUT, CH);
    gather_out_kernel<<<(NN + 7) / 8, T>>>(rowptr, csr, dis, wsum, t, rowvec, b2, out);
}

// round 14
// speedup vs baseline: 1.3254x; 1.0046x over previous
#include <cuda_runtime.h>
#include <math.h>
#include <stddef.h>
#include <stdint.h>

#define NN   100000
#define EE   800000
#define CH   256
#define COUT 40
#define BN_EPS 1e-5f
#define SCAN_BLK 1024
#define NSCAN ((NN + SCAN_BLK - 1) / SCAN_BLK)  // 98

// ---------------- scratch (device globals) ----------------
__device__ float g_t[(size_t)NN * CH];    // GEMM output, pre-scaled by dis[row]
__device__ float g_agg[(size_t)NN * CH];  // aggregated (GCN output pre-BN)
__device__ float g_dis[NN];
__device__ float g_wsum[NN];
__device__ int   g_deg[NN];
__device__ int   g_rowptr[NN + 1];
__device__ int   g_cursor[NN];
__device__ int   g_csr_src[EE];
__device__ int   g_partials[256];
__device__ float g_stats[2 * CH];
__device__ float g_bn_a[CH];
__device__ float g_bn_b[CH];
__device__ float g_pool[CH];
__device__ float g_vx[CH];
__device__ float g_rowvec[CH];
__device__ float g_z[CH];

// ---------------- helpers ----------------
__device__ __forceinline__ uint32_t f2tf32(float x) {
    uint32_t u;
    asm("cvt.rna.tf32.f32 %0, %1;" : "=r"(u) : "f"(x));
    return u;
}

__device__ __forceinline__ void mma_tf32(float& c0, float& c1, float& c2, float& c3,
                                         uint32_t a0, uint32_t a1, uint32_t a2, uint32_t a3,
                                         uint32_t b0, uint32_t b1) {
    asm volatile("mma.sync.aligned.m16n8k8.row.col.f32.tf32.tf32.f32 "
                 "{%0,%1,%2,%3}, {%4,%5,%6,%7}, {%8,%9}, {%0,%1,%2,%3};"
                 : "+f"(c0), "+f"(c1), "+f"(c2), "+f"(c3)
                 : "r"(a0), "r"(a1), "r"(a2), "r"(a3), "r"(b0), "r"(b1));
}

// ---------------- degree / init ----------------
__global__ void zero_deg_kernel(int* __restrict__ deg, float* __restrict__ stats,
                                float* __restrict__ pool, float* __restrict__ rowvec) {
    int i = blockIdx.x * blockDim.x + threadIdx.x;
    if (i < NN) deg[i] = 0;
    if (i < CH) {
        stats[i] = 0.f;
        stats[i + CH] = 0.f;
        pool[i] = 0.f;
        rowvec[i] = 0.f;
    }
}
__global__ void count_deg_kernel(const int* __restrict__ dst, int* __restrict__ deg) {
    int e = blockIdx.x * blockDim.x + threadIdx.x;
    if (e < EE) atomicAdd(&deg[dst[e]], 1);
}
__global__ void compute_dis_kernel(const int* __restrict__ deg, float* __restrict__ dis) {
    int i = blockIdx.x * blockDim.x + threadIdx.x;
    if (i < NN) dis[i] = rsqrtf((float)deg[i] + 1.0f);
}

// wsum[n] = dis[n] * (dis[n] + sum_{e into n} dis[src])
__global__ void compute_wsum_kernel(const int* __restrict__ rp, const int* __restrict__ csr,
                                    const float* __restrict__ dis, float* __restrict__ wsum) {
    int n = blockIdx.x * blockDim.x + threadIdx.x;
    if (n >= NN) return;
    float dn = dis[n];
    float s = dn;
    int e1 = rp[n + 1];
    for (int e = rp[n]; e < e1; e++) s += dis[csr[e]];
    wsum[n] = dn * s;
}

// ---------------- exclusive scan (3 phases) ----------------
__global__ void scan1_kernel(const int* __restrict__ deg, int* __restrict__ rp,
                             int* __restrict__ partials) {
    __shared__ int sm[256];
    int tid = threadIdx.x;
    int base = blockIdx.x * SCAN_BLK + tid * 4;
    int v[4];
    int s = 0;
#pragma unroll
    for (int i = 0; i < 4; i++) {
        v[i] = (base + i < NN) ? deg[base + i] : 0;
        s += v[i];
    }
    sm[tid] = s;
    __syncthreads();
#pragma unroll
    for (int off = 1; off < 256; off <<= 1) {
        int tv = (tid >= off) ? sm[tid - off] : 0;
        __syncthreads();
        sm[tid] += tv;
        __syncthreads();
    }
    int excl = sm[tid] - s;
    if (tid == 255) partials[blockIdx.x] = sm[255];
    int run = excl;
#pragma unroll
    for (int i = 0; i < 4; i++) {
        if (base + i < NN) rp[base + i] = run;
        run += v[i];
    }
}

__global__ void scan2_kernel(int* __restrict__ partials) {
    __shared__ int sm[128];
    int tid = threadIdx.x;
    int v = (tid < NSCAN) ? partials[tid] : 0;
    sm[tid] = v;
    __syncthreads();
#pragma unroll
    for (int off = 1; off < 128; off <<= 1) {
        int tv = (tid >= off) ? sm[tid - off] : 0;
        __syncthreads();
        sm[tid] += tv;
        __syncthreads();
    }
    if (tid < NSCAN) partials[tid] = sm[tid] - v;
}

__global__ void scan3_kernel(int* __restrict__ rp, const int* __restrict__ partials,
                             int* __restrict__ cursor) {
    int tid = threadIdx.x;
    int base = blockIdx.x * SCAN_BLK + tid * 4;
    int off = partials[blockIdx.x];
#pragma unroll
    for (int i = 0; i < 4; i++) {
        int idx = base + i;
        if (idx < NN) {
            int val = rp[idx] + off;
            rp[idx] = val;
            cursor[idx] = val;
        }
    }
    if (blockIdx.x == 0 && tid == 0) rp[NN] = EE;
}

__global__ void fill_csr_kernel(const int* __restrict__ src, const int* __restrict__ dst,
                                int* __restrict__ cursor, int* __restrict__ csr) {
    int e = blockIdx.x * blockDim.x + threadIdx.x;
    if (e >= EE) return;
    int slot = atomicAdd(&cursor[dst[e]], 1);
    csr[slot] = src[e];
}

// ---------------- tf32 tensor-core GEMM, double-buffered, dis-scaled fp32 output ----------------
// t'[m] = (op(A) @ B)[m] * dis[m]; op(A) optionally BN+ReLU per column.
template <int BN_T, bool APPLY_BN>
__global__ void __launch_bounds__(256, 2)
mma_gemm_kernel(const float* __restrict__ A, const float* __restrict__ B,
                const float* __restrict__ dis,
                const float* __restrict__ bn_a, const float* __restrict__ bn_b,
                float* __restrict__ Tout,
                int M, int Ncols, int K) {
    constexpr int BM = 128, BK = 16;
    constexpr int AS_STRIDE = BK + 4;          // 20: 20*g mod 32 is a permutation -> conflict-free frags
    constexpr int BS_STRIDE = BN_T + 8;
    constexpr int A_IT = (BM * BK / 4) / 256;  // 2
    constexpr int B_ELEMS4 = BK * BN_T / 4;
    constexpr int B_IT = (B_ELEMS4 + 255) / 256;
    __shared__ uint32_t As[2][BM * AS_STRIDE];
    __shared__ uint32_t Bs[2][BK * BS_STRIDE];

    const int tid = threadIdx.x;
    const int wid = tid >> 5, lane = tid & 31;
    const int gid = lane >> 2, tig = lane & 3;
    const int wm = wid & 3, wn = wid >> 2;
    constexpr int WM = 32, WN = BN_T / 2;
    constexpr int MT = WM / 16;
    constexpr int NT = WN / 8;
    const int m0 = blockIdx.y * BM, n0 = blockIdx.x * BN_T;

    float acc[MT][NT][4];
#pragma unroll
    for (int i = 0; i < MT; i++)
#pragma unroll
        for (int j = 0; j < NT; j++)
#pragma unroll
            for (int q = 0; q < 4; q++) acc[i][j][q] = 0.0f;

    float4 aReg[A_IT], bReg[B_IT];

    auto load_regs = [&](int k0) {
#pragma unroll
        for (int j = 0; j < A_IT; j++) {
            int idx = tid + j * 256;
            int r = idx >> 2, c4 = (idx & 3) * 4;
            int row = m0 + r;
            aReg[j] = (row < M)
                          ? *reinterpret_cast<const float4*>(&A[(size_t)row * K + k0 + c4])
                          : make_float4(0.f, 0.f, 0.f, 0.f);
        }
#pragma unroll
        for (int j = 0; j < B_IT; j++) {
            int idx = tid + j * 256;
            float4 v = make_float4(0.f, 0.f, 0.f, 0.f);
            if (idx < B_ELEMS4) {
                int kr = idx / (BN_T / 4), c4 = (idx % (BN_T / 4)) * 4;
                int col = n0 + c4;
                if (col + 4 <= Ncols)
                    v = *reinterpret_cast<const float4*>(&B[(size_t)(k0 + kr) * Ncols + col]);
            }
            bReg[j] = v;
        }
    };

    auto store_tiles = [&](int buf, int k0) {
#pragma unroll
        for (int j = 0; j < A_IT; j++) {
            int idx = tid + j * 256;
            int r = idx >> 2, c4 = (idx & 3) * 4;
            float4 v = aReg[j];
            if (APPLY_BN) {
                float4 ba = *reinterpret_cast<const float4*>(&bn_a[k0 + c4]);
                float4 bb = *reinterpret_cast<const float4*>(&bn_b[k0 + c4]);
                v.x = fmaxf(fmaf(v.x, ba.x, bb.x), 0.f);
                v.y = fmaxf(fmaf(v.y, ba.y, bb.y), 0.f);
                v.z = fmaxf(fmaf(v.z, ba.z, bb.z), 0.f);
                v.w = fmaxf(fmaf(v.w, ba.w, bb.w), 0.f);
            }
            uint4 u = make_uint4(f2tf32(v.x), f2tf32(v.y), f2tf32(v.z), f2tf32(v.w));
            *reinterpret_cast<uint4*>(&As[buf][r * AS_STRIDE + c4]) = u;
        }
#pragma unroll
        for (int j = 0; j < B_IT; j++) {
            int idx = tid + j * 256;
            if (idx < B_ELEMS4) {
                int kr = idx / (BN_T / 4), c4 = (idx % (BN_T / 4)) * 4;
                float4 v = bReg[j];
                uint4 u = make_uint4(f2tf32(v.x), f2tf32(v.y), f2tf32(v.z), f2tf32(v.w));
                *reinterpret_cast<uint4*>(&Bs[buf][kr * BS_STRIDE + c4]) = u;
            }
        }
    };

    // prologue
    load_regs(0);
    store_tiles(0, 0);
    __syncthreads();

    const int KT = K / BK;
    for (int kt = 0; kt < KT; kt++) {
        int cur = kt & 1;
        if (kt + 1 < KT) load_regs((kt + 1) * BK);  // prefetch next tile (latency hidden by mma)

#pragma unroll
        for (int k8 = 0; k8 < BK; k8 += 8) {
            uint32_t bf[NT][2];
#pragma unroll
            for (int nt = 0; nt < NT; nt++) {
                int ncol = wn * WN + nt * 8 + gid;
                bf[nt][0] = Bs[cur][(k8 + tig) * BS_STRIDE + ncol];
                bf[nt][1] = Bs[cur][(k8 + tig + 4) * BS_STRIDE + ncol];
            }
#pragma unroll
            for (int mt = 0; mt < MT; mt++) {
                int mrow = wm * WM + mt * 16 + gid;
                uint32_t a0 = As[cur][mrow * AS_STRIDE + k8 + tig];
                uint32_t a1 = As[cur][(mrow + 8) * AS_STRIDE + k8 + tig];
                uint32_t a2 = As[cur][mrow * AS_STRIDE + k8 + tig + 4];
                uint32_t a3 = As[cur][(mrow + 8) * AS_STRIDE + k8 + tig + 4];
#pragma unroll
                for (int nt = 0; nt < NT; nt++)
                    mma_tf32(acc[mt][nt][0], acc[mt][nt][1], acc[mt][nt][2], acc[mt][nt][3],
                             a0, a1, a2, a3, bf[nt][0], bf[nt][1]);
            }
        }

        if (kt + 1 < KT) store_tiles(cur ^ 1, (kt + 1) * BK);
        __syncthreads();
    }

#pragma unroll
    for (int mt = 0; mt < MT; mt++) {
        int r0 = m0 + wm * WM + mt * 16 + gid;
        int r1 = r0 + 8;
        float d0 = (r0 < M) ? dis[r0] : 0.f;
        float d1 = (r1 < M) ? dis[r1] : 0.f;
#pragma unroll
        for (int nt = 0; nt < NT; nt++) {
            int col = n0 + wn * WN + nt * 8 + tig * 2;
            if (col + 2 > Ncols) continue;
            if (r0 < M)
                *reinterpret_cast<float2*>(&Tout[(size_t)r0 * Ncols + col]) =
                    make_float2(acc[mt][nt][0] * d0, acc[mt][nt][1] * d0);
            if (r1 < M)
                *reinterpret_cast<float2*>(&Tout[(size_t)r1 * Ncols + col]) =
                    make_float2(acc[mt][nt][2] * d1, acc[mt][nt][3] * d1);
        }
    }
}

// ---------------- CSR gather aggregation (C=256, dis-scaled t) + fused BN stats ----------------
// agg[n] = dis[n]*(t'[n] + sum_src t'[src]) + rowvec[c]*wsum[n] + bias[c]
#define GATHER_G 16
__global__ void __launch_bounds__(256)
gather_wide_kernel(const int* __restrict__ rp, const int* __restrict__ csr,
                   const float* __restrict__ dis, const float* __restrict__ wsum,
                   const float* __restrict__ t,
                   const float* __restrict__ rowvec, const float* __restrict__ bias,
                   float* __restrict__ agg, float* __restrict__ stats) {
    int c = threadIdx.x;
    float b = bias[c];
    float rv = rowvec[c];
    float s1 = 0.f, s2 = 0.f;
    int n0 = blockIdx.x * GATHER_G;
#pragma unroll 1
    for (int g = 0; g < GATHER_G; g++) {
        int n = n0 + g;
        if (n >= NN) break;
        float acc = t[(size_t)n * CH + c];  // self term (already dis-scaled)
        int e = rp[n], e1 = rp[n + 1];
        for (; e + 2 <= e1; e += 2) {
            int sa = csr[e];
            int sb = csr[e + 1];
            float va = t[(size_t)sa * CH + c];
            float vb = t[(size_t)sb * CH + c];
            acc += va + vb;
        }
        if (e < e1) {
            int sa = csr[e];
            acc += t[(size_t)sa * CH + c];
        }
        acc = fmaf(acc, dis[n], fmaf(rv, wsum[n], b));
        agg[(size_t)n * CH + c] = acc;
        s1 += acc;
        s2 += acc * acc;
    }
    atomicAdd(&stats[c], s1);
    atomicAdd(&stats[CH + c], s2);
}

// ---------------- BN finalize (also initializes z = vnb for the VN matvec) ----------------
__global__ void finalize_stats_kernel(const float* __restrict__ stats,
                                      const float* __restrict__ g, const float* __restrict__ bv,
                                      const float* __restrict__ vnb,
                                      float* __restrict__ bn_a, float* __restrict__ bn_b,
                                      float* __restrict__ z) {
    int c = threadIdx.x;
    float m = stats[c] * (1.0f / (float)NN);
    float v = stats[CH + c] * (1.0f / (float)NN) - m * m;
    float a = rsqrtf(v + BN_EPS) * g[c];
    bn_a[c] = a;
    bn_b[c] = bv[c] - m * a;
    z[c] = vnb[c];
}

__global__ void pool_kernel(const float* __restrict__ agg,
                            const float* __restrict__ bn_a, const float* __restrict__ bn_b,
                            float* __restrict__ pool) {
    int c = threadIdx.x;
    float a = bn_a[c], b = bn_b[c];
    float ps = 0.f;
    for (int r = blockIdx.x; r < NN; r += gridDim.x)
        ps += fmaxf(fmaf(agg[(size_t)r * CH + c], a, b), 0.f);
    atomicAdd(&pool[c], ps);
}

// ---------------- virtual-node MLP ----------------
__global__ void vn_matvec_kernel(const float* __restrict__ pool, const float* __restrict__ vx_prev,
                                 const float* __restrict__ W, float* __restrict__ z, int cols) {
    __shared__ float ss[32];
    int c = threadIdx.x;
    int kb = blockIdx.x * 32;
    if (c < 32) ss[c] = pool[kb + c] + vx_prev[kb + c];
    __syncthreads();
    if (c < cols) {
        float acc = 0.f;
#pragma unroll
        for (int k = 0; k < 32; k++) acc = fmaf(ss[k], W[(size_t)(kb + k) * cols + c], acc);
        atomicAdd(&z[c], acc);
    }
}

// LayerNorm+ReLU; re-zeros stats/pool/rowvec for the next layer
__global__ void vn_ln_kernel(const float* __restrict__ z,
                             const float* __restrict__ lng, const float* __restrict__ lnb,
                             float* __restrict__ vx_out, float* __restrict__ rowvec,
                             float* __restrict__ stats, float* __restrict__ pool) {
    __shared__ float red[CH];
    int c = threadIdx.x;
    float zv = z[c];
    red[c] = zv;
    __syncthreads();
    for (int off = CH / 2; off; off >>= 1) {
        if (c < off) red[c] += red[c + off];
        __syncthreads();
    }
    float mu = red[0] * (1.0f / (float)CH);
    __syncthreads();
    float d = zv - mu;
    red[c] = d * d;
    __syncthreads();
    for (int off = CH / 2; off; off >>= 1) {
        if (c < off) red[c] += red[c + off];
        __syncthreads();
    }
    float var = red[0] * (1.0f / (float)CH);
    vx_out[c] = fmaxf(fmaf(d * rsqrtf(var + BN_EPS), lng[c], lnb[c]), 0.f);
    rowvec[c] = 0.f;
    stats[c] = 0.f;
    stats[CH + c] = 0.f;
    pool[c] = 0.f;
}

__global__ void rowvec_matvec_kernel(const float* __restrict__ vx, const float* __restrict__ W,
                                     float* __restrict__ rowvec, int cols) {
    __shared__ float ss[32];
    int c = threadIdx.x;
    int kb = blockIdx.x * 32;
    if (c < 32) ss[c] = vx[kb + c];
    __syncthreads();
    if (c < cols) {
        float acc = 0.f;
#pragma unroll
        for (int k = 0; k < 32; k++) acc = fmaf(ss[k], W[(size_t)(kb + k) * cols + c], acc);
        atomicAdd(&rowvec[c], acc);
    }
}

// ---------------- final layer: CSR gather (C=40, dis-scaled t) + log_softmax ----------------
__global__ void __launch_bounds__(256)
gather_out_kernel(const int* __restrict__ rp, const int* __restrict__ csr,
                  const float* __restrict__ dis, const float* __restrict__ wsum,
                  const float* __restrict__ t,
                  const float* __restrict__ rowvec, const float* __restrict__ bias,
                  float* __restrict__ out) {
    int warp = threadIdx.x >> 5;
    int lane = threadIdx.x & 31;
    int n = blockIdx.x * 8 + warp;
    if (n >= NN) return;

    const float* tn = t + (size_t)n * COUT;
    float acc0 = tn[lane];
    float acc1 = (lane < COUT - 32) ? tn[32 + lane] : 0.f;

    int e = rp[n], e1 = rp[n + 1];
    for (; e + 2 <= e1; e += 2) {
        int sa = csr[e];
        int sb = csr[e + 1];
        const float* ta = t + (size_t)sa * COUT;
        const float* tb = t + (size_t)sb * COUT;
        acc0 += ta[lane] + tb[lane];
        if (lane < COUT - 32) acc1 += ta[32 + lane] + tb[32 + lane];
    }
    if (e < e1) {
        int sa = csr[e];
        const float* ta = t + (size_t)sa * COUT;
        acc0 += ta[lane];
        if (lane < COUT - 32) acc1 += ta[32 + lane];
    }

    float dn = dis[n];
    float ws = wsum[n];
    acc0 = fmaf(acc0, dn, fmaf(rowvec[lane], ws, bias[lane]));
    acc1 = (lane < COUT - 32)
               ? fmaf(acc1, dn, fmaf(rowvec[32 + lane], ws, bias[32 + lane]))
               : -1e30f;

    float m = fmaxf(acc0, acc1);
#pragma unroll
    for (int off = 16; off; off >>= 1) m = fmaxf(m, __shfl_xor_sync(0xffffffffu, m, off));
    float sum = expf(acc0 - m) + ((lane < COUT - 32) ? expf(acc1 - m) : 0.f);
#pragma unroll
    for (int off = 16; off; off >>= 1) sum += __shfl_xor_sync(0xffffffffu, sum, off);
    float l = m + logf(sum);
    out[(size_t)n * COUT + lane] = acc0 - l;
    if (lane < COUT - 32) out[(size_t)n * COUT + 32 + lane] = acc1 - l;
}

// ---------------- driver ----------------
extern "C" void kernel_launch(void* const* d_in, const int* in_sizes, int n_in,
                              void* d_out, int out_size) {
    const float* x      = (const float*)d_in[0];
    const int*   ei     = (const int*)d_in[1];
    const float* W0     = (const float*)d_in[2];
    const float* b0     = (const float*)d_in[3];
    const float* W1     = (const float*)d_in[4];
    const float* b1     = (const float*)d_in[5];
    const float* W2     = (const float*)d_in[6];
    const float* b2     = (const float*)d_in[7];
    const float* bn_g0  = (const float*)d_in[8];
    const float* bn_b0  = (const float*)d_in[9];
    const float* bn_g1  = (const float*)d_in[10];
    const float* bn_b1  = (const float*)d_in[11];
    const float* vn_emb = (const float*)d_in[12];
    const float* vn_W0  = (const float*)d_in[13];
    const float* vn_b0  = (const float*)d_in[14];
    const float* ln_g0  = (const float*)d_in[15];
    const float* ln_b0  = (const float*)d_in[16];
    const float* vn_W1  = (const float*)d_in[17];
    const float* vn_b1  = (const float*)d_in[18];
    const float* ln_g1  = (const float*)d_in[19];
    const float* ln_b1  = (const float*)d_in[20];
    float* out = (float*)d_out;

    const int* src = ei;
    const int* dst = ei + EE;

    float *t, *agg, *dis, *wsum, *stats, *bn_a, *bn_b, *pool, *vx, *rowvec, *z;
    int *deg, *rowptr, *cursor, *csr, *partials;
    cudaGetSymbolAddress((void**)&t, g_t);
    cudaGetSymbolAddress((void**)&agg, g_agg);
    cudaGetSymbolAddress((void**)&dis, g_dis);
    cudaGetSymbolAddress((void**)&wsum, g_wsum);
    cudaGetSymbolAddress((void**)&deg, g_deg);
    cudaGetSymbolAddress((void**)&rowptr, g_rowptr);
    cudaGetSymbolAddress((void**)&cursor, g_cursor);
    cudaGetSymbolAddress((void**)&csr, g_csr_src);
    cudaGetSymbolAddress((void**)&partials, g_partials);
    cudaGetSymbolAddress((void**)&stats, g_stats);
    cudaGetSymbolAddress((void**)&bn_a, g_bn_a);
    cudaGetSymbolAddress((void**)&bn_b, g_bn_b);
    cudaGetSymbolAddress((void**)&pool, g_pool);
    cudaGetSymbolAddress((void**)&vx, g_vx);
    cudaGetSymbolAddress((void**)&rowvec, g_rowvec);
    cudaGetSymbolAddress((void**)&z, g_z);

    const int T = 256;
    const int STAT_BLOCKS = 1024;
    dim3 gemm_wide(CH / 128, (NN + 127) / 128);
    dim3 gemm_narrow(1, (NN + 127) / 128);
    int gather_blocks = (NN + GATHER_G - 1) / GATHER_G;

    // ---- prologue; wide GEMM placed at launch #4 so ncu (-s3/-c1) captures it ----
    zero_deg_kernel<<<(NN + T - 1) / T, T>>>(deg, stats, pool, rowvec);       // 1
    count_deg_kernel<<<(EE + T - 1) / T, T>>>(dst, deg);                      // 2
    compute_dis_kernel<<<(NN + T - 1) / T, T>>>(deg, dis);                    // 3
    mma_gemm_kernel<128, false><<<gemm_wide, T>>>(x, W0, dis,                 // 4
                                                  nullptr, nullptr, t, NN, CH, CH);
    rowvec_matvec_kernel<<<8, T>>>(vn_emb, W0, rowvec, CH);                   // 5
    scan1_kernel<<<NSCAN, 256>>>(deg, rowptr, partials);                      // 6
    scan2_kernel<<<1, 128>>>(partials);                                       // 7
    scan3_kernel<<<NSCAN, 256>>>(rowptr, partials, cursor);                   // 8
    fill_csr_kernel<<<(EE + T - 1) / T, T>>>(src, dst, cursor, csr);          // 9
    compute_wsum_kernel<<<(NN + T - 1) / T, T>>>(rowptr, csr, dis, wsum);     // 10

    // ---- layer 0 ----
    gather_wide_kernel<<<gather_blocks, T>>>(rowptr, csr, dis, wsum, t, rowvec, b0, agg, stats);
    finalize_stats_kernel<<<1, T>>>(stats, bn_g0, bn_b0, vn_b0, bn_a, bn_b, z);
    pool_kernel<<<STAT_BLOCKS, T>>>(agg, bn_a, bn_b, pool);
    vn_matvec_kernel<<<8, T>>>(pool, vn_emb, vn_W0, z, CH);
    vn_ln_kernel<<<1, T>>>(z, ln_g0, ln_b0, vx, rowvec, stats, pool);
    rowvec_matvec_kernel<<<8, T>>>(vx, W1, rowvec, CH);

    // ---- layer 1 ----
    mma_gemm_kernel<128, true><<<gemm_wide, T>>>(agg, W1, dis, bn_a, bn_b, t, NN, CH, CH);
    gather_wide_kernel<<<gather_blocks, T>>>(rowptr, csr, dis, wsum, t, rowvec, b1, agg, stats);
    finalize_stats_kernel<<<1, T>>>(stats, bn_g1, bn_b1, vn_b1, bn_a, bn_b, z);
    pool_kernel<<<STAT_BLOCKS, T>>>(agg, bn_a, bn_b, pool);
    vn_matvec_kernel<<<8, T>>>(pool, vx, vn_W1, z, CH);
    vn_ln_kernel<<<1, T>>>(z, ln_g1, ln_b1, vx, rowvec, stats, pool);
    rowvec_matvec_kernel<<<8, T>>>(vx, W2, rowvec, COUT);

    // ---- layer 2 (output, 48-col tile over 40 cols, fused gather + log_softmax) ----
    mma_gemm_kernel<48, true><<<gemm_narrow, T>>>(agg, W2, dis, bn_a, bn_b, t, NN, COUT, CH);
    gather_out_kernel<<<(NN + 7) / 8, T>>>(rowptr, csr, dis, wsum, t, rowvec, b2, out);
}

// round 15
// speedup vs baseline: 1.3712x; 1.0345x over previous
#include <cuda_runtime.h>
#include <math.h>
#include <stddef.h>
#include <stdint.h>

#define NN   100000
#define EE   800000
#define CH   256
#define COUT 40
#define BN_EPS 1e-5f
#define SCAN_BLK 1024
#define NSCAN ((NN + SCAN_BLK - 1) / SCAN_BLK)  // 98

// ---------------- scratch (device globals) ----------------
__device__ float g_t[(size_t)NN * CH];    // GEMM output, pre-scaled by dis[row]
__device__ float g_agg[(size_t)NN * CH];  // aggregated (GCN output pre-BN)
__device__ float g_h[(size_t)NN * CH];    // post-BN/ReLU activations
__device__ float g_dis[NN];
__device__ float g_wsum[NN];
__device__ int   g_deg[NN];
__device__ int   g_rowptr[NN + 1];
__device__ int   g_cursor[NN];
__device__ int   g_csr_src[EE];
__device__ int   g_partials[256];
__device__ float g_stats[2 * CH];
__device__ float g_bn_a[CH];
__device__ float g_bn_b[CH];
__device__ float g_pool[CH];
__device__ float g_vx[CH];
__device__ float g_rowvec[CH];
__device__ float g_z[CH];

// ---------------- helpers ----------------
__device__ __forceinline__ void mma_tf32(float& c0, float& c1, float& c2, float& c3,
                                         uint32_t a0, uint32_t a1, uint32_t a2, uint32_t a3,
                                         uint32_t b0, uint32_t b1) {
    asm volatile("mma.sync.aligned.m16n8k8.row.col.f32.tf32.tf32.f32 "
                 "{%0,%1,%2,%3}, {%4,%5,%6,%7}, {%8,%9}, {%0,%1,%2,%3};"
                 : "+f"(c0), "+f"(c1), "+f"(c2), "+f"(c3)
                 : "r"(a0), "r"(a1), "r"(a2), "r"(a3), "r"(b0), "r"(b1));
}

__device__ __forceinline__ void cp_async16(uint32_t smem_addr, const void* gptr, int src_bytes) {
    asm volatile("cp.async.cg.shared.global [%0], [%1], 16, %2;"
                 :: "r"(smem_addr), "l"(gptr), "r"(src_bytes) : "memory");
}

// ---------------- degree / init ----------------
__global__ void zero_deg_kernel(int* __restrict__ deg, float* __restrict__ stats,
                                float* __restrict__ pool, float* __restrict__ rowvec) {
    int i = blockIdx.x * blockDim.x + threadIdx.x;
    if (i < NN) deg[i] = 0;
    if (i < CH) {
        stats[i] = 0.f;
        stats[i + CH] = 0.f;
        pool[i] = 0.f;
        rowvec[i] = 0.f;
    }
}
__global__ void count_deg_kernel(const int* __restrict__ dst, int* __restrict__ deg) {
    int e = blockIdx.x * blockDim.x + threadIdx.x;
    if (e < EE) atomicAdd(&deg[dst[e]], 1);
}
__global__ void compute_dis_kernel(const int* __restrict__ deg, float* __restrict__ dis) {
    int i = blockIdx.x * blockDim.x + threadIdx.x;
    if (i < NN) dis[i] = rsqrtf((float)deg[i] + 1.0f);
}

// wsum[n] = dis[n] * (dis[n] + sum_{e into n} dis[src])
__global__ void compute_wsum_kernel(const int* __restrict__ rp, const int* __restrict__ csr,
                                    const float* __restrict__ dis, float* __restrict__ wsum) {
    int n = blockIdx.x * blockDim.x + threadIdx.x;
    if (n >= NN) return;
    float dn = dis[n];
    float s = dn;
    int e1 = rp[n + 1];
    for (int e = rp[n]; e < e1; e++) s += dis[csr[e]];
    wsum[n] = dn * s;
}

// ---------------- exclusive scan (3 phases) ----------------
__global__ void scan1_kernel(const int* __restrict__ deg, int* __restrict__ rp,
                             int* __restrict__ partials) {
    __shared__ int sm[256];
    int tid = threadIdx.x;
    int base = blockIdx.x * SCAN_BLK + tid * 4;
    int v[4];
    int s = 0;
#pragma unroll
    for (int i = 0; i < 4; i++) {
        v[i] = (base + i < NN) ? deg[base + i] : 0;
        s += v[i];
    }
    sm[tid] = s;
    __syncthreads();
#pragma unroll
    for (int off = 1; off < 256; off <<= 1) {
        int tv = (tid >= off) ? sm[tid - off] : 0;
        __syncthreads();
        sm[tid] += tv;
        __syncthreads();
    }
    int excl = sm[tid] - s;
    if (tid == 255) partials[blockIdx.x] = sm[255];
    int run = excl;
#pragma unroll
    for (int i = 0; i < 4; i++) {
        if (base + i < NN) rp[base + i] = run;
        run += v[i];
    }
}

__global__ void scan2_kernel(int* __restrict__ partials) {
    __shared__ int sm[128];
    int tid = threadIdx.x;
    int v = (tid < NSCAN) ? partials[tid] : 0;
    sm[tid] = v;
    __syncthreads();
#pragma unroll
    for (int off = 1; off < 128; off <<= 1) {
        int tv = (tid >= off) ? sm[tid - off] : 0;
        __syncthreads();
        sm[tid] += tv;
        __syncthreads();
    }
    if (tid < NSCAN) partials[tid] = sm[tid] - v;
}

__global__ void scan3_kernel(int* __restrict__ rp, const int* __restrict__ partials,
                             int* __restrict__ cursor) {
    int tid = threadIdx.x;
    int base = blockIdx.x * SCAN_BLK + tid * 4;
    int off = partials[blockIdx.x];
#pragma unroll
    for (int i = 0; i < 4; i++) {
        int idx = base + i;
        if (idx < NN) {
            int val = rp[idx] + off;
            rp[idx] = val;
            cursor[idx] = val;
        }
    }
    if (blockIdx.x == 0 && tid == 0) rp[NN] = EE;
}

__global__ void fill_csr_kernel(const int* __restrict__ src, const int* __restrict__ dst,
                                int* __restrict__ cursor, int* __restrict__ csr) {
    int e = blockIdx.x * blockDim.x + threadIdx.x;
    if (e >= EE) return;
    int slot = atomicAdd(&cursor[dst[e]], 1);
    csr[slot] = src[e];
}

// ---------------- tf32 tensor-core GEMM, cp.async double-buffered ----------------
// t'[m] = (A @ B)[m] * dis[m]. fp32 fed raw to mma.tf32 (HW truncates to tf32).
template <int BN_T>
__global__ void __launch_bounds__(256, 2)
mma_gemm_kernel(const float* __restrict__ A, const float* __restrict__ B,
                const float* __restrict__ dis, float* __restrict__ Tout,
                int M, int Ncols, int K) {
    constexpr int BM = 128, BK = 16;
    constexpr int AS_STRIDE = BK + 4;          // 20 -> conflict-free A frags
    constexpr int BS_STRIDE = BN_T + 8;        // stride%32==8 -> conflict-free B frags
    constexpr int A_IT = (BM * BK / 4) / 256;  // 2
    constexpr int B_ELEMS4 = BK * BN_T / 4;
    constexpr int B_IT = (B_ELEMS4 + 255) / 256;
    __shared__ uint32_t As[2][BM * AS_STRIDE];
    __shared__ uint32_t Bs[2][BK * BS_STRIDE];

    const int tid = threadIdx.x;
    const int wid = tid >> 5, lane = tid & 31;
    const int gid = lane >> 2, tig = lane & 3;
    const int wm = wid & 3, wn = wid >> 2;
    constexpr int WM = 32, WN = BN_T / 2;
    constexpr int MT = WM / 16;
    constexpr int NT = WN / 8;
    const int m0 = blockIdx.y * BM, n0 = blockIdx.x * BN_T;

    // ---- hoisted cp.async addressing ----
    const float* aSrc[A_IT];
    uint32_t aDst[2][A_IT];
    int aPred[A_IT];
#pragma unroll
    for (int j = 0; j < A_IT; j++) {
        int idx = tid + j * 256;
        int r = idx >> 2, c4 = (idx & 3) * 4;
        int row = m0 + r;
        aSrc[j] = &A[(size_t)(row < M ? row : 0) * K + c4];
        aPred[j] = (row < M) ? 16 : 0;
        aDst[0][j] = (uint32_t)__cvta_generic_to_shared(&As[0][r * AS_STRIDE + c4]);
        aDst[1][j] = (uint32_t)__cvta_generic_to_shared(&As[1][r * AS_STRIDE + c4]);
    }
    const float* bSrc[B_IT];
    uint32_t bDst[2][B_IT];
    int bPred[B_IT];
#pragma unroll
    for (int j = 0; j < B_IT; j++) {
        int idx = tid + j * 256;
        int kr = 0, c4 = 0, col = 0;
        int ok = (idx < B_ELEMS4);
        if (ok) {
            kr = idx / (BN_T / 4);
            c4 = (idx % (BN_T / 4)) * 4;
            col = n0 + c4;
        }
        bSrc[j] = &B[(size_t)kr * Ncols + (col + 4 <= Ncols ? col : 0)];
        bPred[j] = (ok && col + 4 <= Ncols) ? 16 : 0;
        bDst[0][j] = (uint32_t)__cvta_generic_to_shared(&Bs[0][kr * BS_STRIDE + c4]);
        bDst[1][j] = (uint32_t)__cvta_generic_to_shared(&Bs[1][kr * BS_STRIDE + c4]);
        if (!ok) bPred[j] = -1;  // sentinel: skip entirely
    }

    auto issue_tile = [&](int buf, int kt) {
        int kOffA = kt * BK;
#pragma unroll
        for (int j = 0; j < A_IT; j++)
            cp_async16(aDst[buf][j], aSrc[j] + kOffA, aPred[j]);
        long long kOffB = (long long)kt * BK * Ncols;
#pragma unroll
        for (int j = 0; j < B_IT; j++)
            if (bPred[j] >= 0) cp_async16(bDst[buf][j], bSrc[j] + kOffB, bPred[j]);
        asm volatile("cp.async.commit_group;" ::: "memory");
    };

    float acc[MT][NT][4];
#pragma unroll
    for (int i = 0; i < MT; i++)
#pragma unroll
        for (int j = 0; j < NT; j++)
#pragma unroll
            for (int q = 0; q < 4; q++) acc[i][j][q] = 0.0f;

    const int KT = K / BK;
    issue_tile(0, 0);

    for (int kt = 0; kt < KT; kt++) {
        int cur = kt & 1;
        if (kt + 1 < KT) {
            issue_tile(cur ^ 1, kt + 1);
            asm volatile("cp.async.wait_group 1;" ::: "memory");
        } else {
            asm volatile("cp.async.wait_group 0;" ::: "memory");
        }
        __syncthreads();  // tile kt visible to all warps

#pragma unroll
        for (int k8 = 0; k8 < BK; k8 += 8) {
            uint32_t bf[NT][2];
#pragma unroll
            for (int nt = 0; nt < NT; nt++) {
                int ncol = wn * WN + nt * 8 + gid;
                bf[nt][0] = Bs[cur][(k8 + tig) * BS_STRIDE + ncol];
                bf[nt][1] = Bs[cur][(k8 + tig + 4) * BS_STRIDE + ncol];
            }
#pragma unroll
            for (int mt = 0; mt < MT; mt++) {
                int mrow = wm * WM + mt * 16 + gid;
                uint32_t a0 = As[cur][mrow * AS_STRIDE + k8 + tig];
                uint32_t a1 = As[cur][(mrow + 8) * AS_STRIDE + k8 + tig];
                uint32_t a2 = As[cur][mrow * AS_STRIDE + k8 + tig + 4];
                uint32_t a3 = As[cur][(mrow + 8) * AS_STRIDE + k8 + tig + 4];
#pragma unroll
                for (int nt = 0; nt < NT; nt++)
                    mma_tf32(acc[mt][nt][0], acc[mt][nt][1], acc[mt][nt][2], acc[mt][nt][3],
                             a0, a1, a2, a3, bf[nt][0], bf[nt][1]);
            }
        }
        __syncthreads();  // all reads of buf `cur` done before tile kt+2 overwrites it
    }

#pragma unroll
    for (int mt = 0; mt < MT; mt++) {
        int r0 = m0 + wm * WM + mt * 16 + gid;
        int r1 = r0 + 8;
        float d0 = (r0 < M) ? dis[r0] : 0.f;
        float d1 = (r1 < M) ? dis[r1] : 0.f;
#pragma unroll
        for (int nt = 0; nt < NT; nt++) {
            int col = n0 + wn * WN + nt * 8 + tig * 2;
            if (col + 2 > Ncols) continue;
            if (r0 < M)
                *reinterpret_cast<float2*>(&Tout[(size_t)r0 * Ncols + col]) =
                    make_float2(acc[mt][nt][0] * d0, acc[mt][nt][1] * d0);
            if (r1 < M)
                *reinterpret_cast<float2*>(&Tout[(size_t)r1 * Ncols + col]) =
                    make_float2(acc[mt][nt][2] * d1, acc[mt][nt][3] * d1);
        }
    }
}

// ---------------- CSR gather aggregation (C=256, dis-scaled t) + fused BN stats ----------------
// agg[n] = dis[n]*(t'[n] + sum_src t'[src]) + rowvec[c]*wsum[n] + bias[c]
#define GATHER_G 16
__global__ void __launch_bounds__(256)
gather_wide_kernel(const int* __restrict__ rp, const int* __restrict__ csr,
                   const float* __restrict__ dis, const float* __restrict__ wsum,
                   const float* __restrict__ t,
                   const float* __restrict__ rowvec, const float* __restrict__ bias,
                   float* __restrict__ agg, float* __restrict__ stats) {
    int c = threadIdx.x;
    float b = bias[c];
    float rv = rowvec[c];
    float s1 = 0.f, s2 = 0.f;
    int n0 = blockIdx.x * GATHER_G;
#pragma unroll 1
    for (int g = 0; g < GATHER_G; g++) {
        int n = n0 + g;
        if (n >= NN) break;
        float acc = t[(size_t)n * CH + c];  // self term (already dis-scaled)
        int e = rp[n], e1 = rp[n + 1];
        for (; e + 2 <= e1; e += 2) {
            int sa = csr[e];
            int sb = csr[e + 1];
            float va = t[(size_t)sa * CH + c];
            float vb = t[(size_t)sb * CH + c];
            acc += va + vb;
        }
        if (e < e1) {
            int sa = csr[e];
            acc += t[(size_t)sa * CH + c];
        }
        acc = fmaf(acc, dis[n], fmaf(rv, wsum[n], b));
        agg[(size_t)n * CH + c] = acc;
        s1 += acc;
        s2 += acc * acc;
    }
    atomicAdd(&stats[c], s1);
    atomicAdd(&stats[CH + c], s2);
}

// ---------------- BN finalize (also initializes z = vnb for the VN matvec) ----------------
__global__ void finalize_stats_kernel(const float* __restrict__ stats,
                                      const float* __restrict__ g, const float* __restrict__ bv,
                                      const float* __restrict__ vnb,
                                      float* __restrict__ bn_a, float* __restrict__ bn_b,
                                      float* __restrict__ z) {
    int c = threadIdx.x;
    float m = stats[c] * (1.0f / (float)NN);
    float v = stats[CH + c] * (1.0f / (float)NN) - m * m;
    float a = rsqrtf(v + BN_EPS) * g[c];
    bn_a[c] = a;
    bn_b[c] = bv[c] - m * a;
    z[c] = vnb[c];
}

// pool + materialize h = relu(bn(agg))  (h feeds the next GEMM, which is now BN-free)
__global__ void pool_kernel(const float* __restrict__ agg,
                            const float* __restrict__ bn_a, const float* __restrict__ bn_b,
                            float* __restrict__ h, float* __restrict__ pool) {
    int c = threadIdx.x;
    float a = bn_a[c], b = bn_b[c];
    float ps = 0.f;
    for (int r = blockIdx.x; r < NN; r += gridDim.x) {
        float v = fmaxf(fmaf(agg[(size_t)r * CH + c], a, b), 0.f);
        h[(size_t)r * CH + c] = v;
        ps += v;
    }
    atomicAdd(&pool[c], ps);
}

// ---------------- virtual-node MLP ----------------
__global__ void vn_matvec_kernel(const float* __restrict__ pool, const float* __restrict__ vx_prev,
                                 const float* __restrict__ W, float* __restrict__ z, int cols) {
    __shared__ float ss[32];
    int c = threadIdx.x;
    int kb = blockIdx.x * 32;
    if (c < 32) ss[c] = pool[kb + c] + vx_prev[kb + c];
    __syncthreads();
    if (c < cols) {
        float acc = 0.f;
#pragma unroll
        for (int k = 0; k < 32; k++) acc = fmaf(ss[k], W[(size_t)(kb + k) * cols + c], acc);
        atomicAdd(&z[c], acc);
    }
}

// LayerNorm+ReLU; re-zeros stats/pool/rowvec for the next layer
__global__ void vn_ln_kernel(const float* __restrict__ z,
                             const float* __restrict__ lng, const float* __restrict__ lnb,
                             float* __restrict__ vx_out, float* __restrict__ rowvec,
                             float* __restrict__ stats, float* __restrict__ pool) {
    __shared__ float red[CH];
    int c = threadIdx.x;
    float zv = z[c];
    red[c] = zv;
    __syncthreads();
    for (int off = CH / 2; off; off >>= 1) {
        if (c < off) red[c] += red[c + off];
        __syncthreads();
    }
    float mu = red[0] * (1.0f / (float)CH);
    __syncthreads();
    float d = zv - mu;
    red[c] = d * d;
    __syncthreads();
    for (int off = CH / 2; off; off >>= 1) {
        if (c < off) red[c] += red[c + off];
        __syncthreads();
    }
    float var = red[0] * (1.0f / (float)CH);
    vx_out[c] = fmaxf(fmaf(d * rsqrtf(var + BN_EPS), lng[c], lnb[c]), 0.f);
    rowvec[c] = 0.f;
    stats[c] = 0.f;
    stats[CH + c] = 0.f;
    pool[c] = 0.f;
}

__global__ void rowvec_matvec_kernel(const float* __restrict__ vx, const float* __restrict__ W,
                                     float* __restrict__ rowvec, int cols) {
    __shared__ float ss[32];
    int c = threadIdx.x;
    int kb = blockIdx.x * 32;
    if (c < 32) ss[c] = vx[kb + c];
    __syncthreads();
    if (c < cols) {
        float acc = 0.f;
#pragma unroll
        for (int k = 0; k < 32; k++) acc = fmaf(ss[k], W[(size_t)(kb + k) * cols + c], acc);
        atomicAdd(&rowvec[c], acc);
    }
}

// ---------------- final layer: CSR gather (C=40, dis-scaled t) + log_softmax ----------------
__global__ void __launch_bounds__(256)
gather_out_kernel(const int* __restrict__ rp, const int* __restrict__ csr,
                  const float* __restrict__ dis, const float* __restrict__ wsum,
                  const float* __restrict__ t,
                  const float* __restrict__ rowvec, const float* __restrict__ bias,
                  float* __restrict__ out) {
    int warp = threadIdx.x >> 5;
    int lane = threadIdx.x & 31;
    int n = blockIdx.x * 8 + warp;
    if (n >= NN) return;

    const float* tn = t + (size_t)n * COUT;
    float acc0 = tn[lane];
    float acc1 = (lane < COUT - 32) ? tn[32 + lane] : 0.f;

    int e = rp[n], e1 = rp[n + 1];
    for (; e + 2 <= e1; e += 2) {
        int sa = csr[e];
        int sb = csr[e + 1];
        const float* ta = t + (size_t)sa * COUT;
        const float* tb = t + (size_t)sb * COUT;
        acc0 += ta[lane] + tb[lane];
        if (lane < COUT - 32) acc1 += ta[32 + lane] + tb[32 + lane];
    }
    if (e < e1) {
        int sa = csr[e];
        const float* ta = t + (size_t)sa * COUT;
        acc0 += ta[lane];
        if (lane < COUT - 32) acc1 += ta[32 + lane];
    }

    float dn = dis[n];
    float ws = wsum[n];
    acc0 = fmaf(acc0, dn, fmaf(rowvec[lane], ws, bias[lane]));
    acc1 = (lane < COUT - 32)
               ? fmaf(acc1, dn, fmaf(rowvec[32 + lane], ws, bias[32 + lane]))
               : -1e30f;

    float m = fmaxf(acc0, acc1);
#pragma unroll
    for (int off = 16; off; off >>= 1) m = fmaxf(m, __shfl_xor_sync(0xffffffffu, m, off));
    float sum = expf(acc0 - m) + ((lane < COUT - 32) ? expf(acc1 - m) : 0.f);
#pragma unroll
    for (int off = 16; off; off >>= 1) sum += __shfl_xor_sync(0xffffffffu, sum, off);
    float l = m + logf(sum);
    out[(size_t)n * COUT + lane] = acc0 - l;
    if (lane < COUT - 32) out[(size_t)n * COUT + 32 + lane] = acc1 - l;
}

// ---------------- driver ----------------
extern "C" void kernel_launch(void* const* d_in, const int* in_sizes, int n_in,
                              void* d_out, int out_size) {
    const float* x      = (const float*)d_in[0];
    const int*   ei     = (const int*)d_in[1];
    const float* W0     = (const float*)d_in[2];
    const float* b0     = (const float*)d_in[3];
    const float* W1     = (const float*)d_in[4];
    const float* b1     = (const float*)d_in[5];
    const float* W2     = (const float*)d_in[6];
    const float* b2     = (const float*)d_in[7];
    const float* bn_g0  = (const float*)d_in[8];
    const float* bn_b0  = (const float*)d_in[9];
    const float* bn_g1  = (const float*)d_in[10];
    const float* bn_b1  = (const float*)d_in[11];
    const float* vn_emb = (const float*)d_in[12];
    const float* vn_W0  = (const float*)d_in[13];
    const float* vn_b0  = (const float*)d_in[14];
    const float* ln_g0  = (const float*)d_in[15];
    const float* ln_b0  = (const float*)d_in[16];
    const float* vn_W1  = (const float*)d_in[17];
    const float* vn_b1  = (const float*)d_in[18];
    const float* ln_g1  = (const float*)d_in[19];
    const float* ln_b1  = (const float*)d_in[20];
    float* out = (float*)d_out;

    const int* src = ei;
    const int* dst = ei + EE;

    float *t, *agg, *h, *dis, *wsum, *stats, *bn_a, *bn_b, *pool, *vx, *rowvec, *z;
    int *deg, *rowptr, *cursor, *csr, *partials;
    cudaGetSymbolAddress((void**)&t, g_t);
    cudaGetSymbolAddress((void**)&agg, g_agg);
    cudaGetSymbolAddress((void**)&h, g_h);
    cudaGetSymbolAddress((void**)&dis, g_dis);
    cudaGetSymbolAddress((void**)&wsum, g_wsum);
    cudaGetSymbolAddress((void**)&deg, g_deg);
    cudaGetSymbolAddress((void**)&rowptr, g_rowptr);
    cudaGetSymbolAddress((void**)&cursor, g_cursor);
    cudaGetSymbolAddress((void**)&csr, g_csr_src);
    cudaGetSymbolAddress((void**)&partials, g_partials);
    cudaGetSymbolAddress((void**)&stats, g_stats);
    cudaGetSymbolAddress((void**)&bn_a, g_bn_a);
    cudaGetSymbolAddress((void**)&bn_b, g_bn_b);
    cudaGetSymbolAddress((void**)&pool, g_pool);
    cudaGetSymbolAddress((void**)&vx, g_vx);
    cudaGetSymbolAddress((void**)&rowvec, g_rowvec);
    cudaGetSymbolAddress((void**)&z, g_z);

    const int T = 256;
    const int STAT_BLOCKS = 1024;
    dim3 gemm_wide(CH / 128, (NN + 127) / 128);
    dim3 gemm_narrow(1, (NN + 127) / 128);
    int gather_blocks = (NN + GATHER_G - 1) / GATHER_G;

    // ---- prologue; wide GEMM placed at launch #4 so ncu (-s3/-c1) captures it ----
    zero_deg_kernel<<<(NN + T - 1) / T, T>>>(deg, stats, pool, rowvec);       // 1
    count_deg_kernel<<<(EE + T - 1) / T, T>>>(dst, deg);                      // 2
    compute_dis_kernel<<<(NN + T - 1) / T, T>>>(deg, dis);                    // 3
    mma_gemm_kernel<128><<<gemm_wide, T>>>(x, W0, dis, t, NN, CH, CH);        // 4
    rowvec_matvec_kernel<<<8, T>>>(vn_emb, W0, rowvec, CH);                   // 5
    scan1_kernel<<<NSCAN, 256>>>(deg, rowptr, partials);                      // 6
    scan2_kernel<<<1, 128>>>(partials);                                       // 7
    scan3_kernel<<<NSCAN, 256>>>(rowptr, partials, cursor);                   // 8
    fill_csr_kernel<<<(EE + T - 1) / T, T>>>(src, dst, cursor, csr);          // 9
    compute_wsum_kernel<<<(NN + T - 1) / T, T>>>(rowptr, csr, dis, wsum);     // 10

    // ---- layer 0 ----
    gather_wide_kernel<<<gather_blocks, T>>>(rowptr, csr, dis, wsum, t, rowvec, b0, agg, stats);
    finalize_stats_kernel<<<1, T>>>(stats, bn_g0, bn_b0, vn_b0, bn_a, bn_b, z);
    pool_kernel<<<STAT_BLOCKS, T>>>(agg, bn_a, bn_b, h, pool);
    vn_matvec_kernel<<<8, T>>>(pool, vn_emb, vn_W0, z, CH);
    vn_ln_kernel<<<1, T>>>(z, ln_g0, ln_b0, vx, rowvec, stats, pool);
    rowvec_matvec_kernel<<<8, T>>>(vx, W1, rowvec, CH);

    // ---- layer 1 ----
    mma_gemm_kernel<128><<<gemm_wide, T>>>(h, W1, dis, t, NN, CH, CH);
    gather_wide_kernel<<<gather_blocks, T>>>(rowptr, csr, dis, wsum, t, rowvec, b1, agg, stats);
    finalize_stats_kernel<<<1, T>>>(stats, bn_g1, bn_b1, vn_b1, bn_a, bn_b, z);
    pool_kernel<<<STAT_BLOCKS, T>>>(agg, bn_a, bn_b, h, pool);
    vn_matvec_kernel<<<8, T>>>(pool, vx, vn_W1, z, CH);
    vn_ln_kernel<<<1, T>>>(z, ln_g1, ln_b1, vx, rowvec, stats, pool);
    rowvec_matvec_kernel<<<8, T>>>(vx, W2, rowvec, COUT);

    // ---- layer 2 (output, 48-col tile over 40 cols, fused gather + log_softmax) ----
    mma_gemm_kernel<48><<<gemm_narrow, T>>>(h, W2, dis, t, NN, COUT, CH);
    gather_out_kernel<<<(NN + 7) / 8, T>>>(rowptr, csr, dis, wsum, t, rowvec, b2, out);
}